// round 8
// baseline (speedup 1.0000x reference)
#include <cuda_runtime.h>
#include <cuda_bf16.h>
#include <math.h>
#include <stdint.h>

#define HID   1024
#define FF    4096
#define NE    8
#define NT    2048
#define NSLOT (NT*2)
#define BM    128
#define BN    64
#define KC    32
#define MAX_TILES 40

// ---------------- scratch (static device globals; no allocation) ------------
__device__ __align__(256) int   g_top_i[NT*2];
__device__ __align__(256) float g_top_w[NT*2];
__device__ __align__(256) int   g_slot_token[NSLOT];
__device__ __align__(256) int   g_token_slot[NT*2];
__device__ __align__(256) int   g_tile_e[MAX_TILES];
__device__ __align__(256) int   g_tile_row0[MAX_TILES];
__device__ __align__(256) int   g_tile_nrows[MAX_TILES];
__device__ int   g_num_tiles;

// bf16 hi/lo planes, native layouts
__device__ __align__(256) __nv_bfloat16 g_xh[NT*HID];
__device__ __align__(256) __nv_bfloat16 g_xl[NT*HID];
__device__ __align__(256) __nv_bfloat16 g_wgh[(size_t)NE*HID*FF];
__device__ __align__(256) __nv_bfloat16 g_wgl[(size_t)NE*HID*FF];
__device__ __align__(256) __nv_bfloat16 g_wuh[(size_t)NE*HID*FF];
__device__ __align__(256) __nv_bfloat16 g_wul[(size_t)NE*HID*FF];
__device__ __align__(256) __nv_bfloat16 g_wdh[(size_t)NE*FF*HID];
__device__ __align__(256) __nv_bfloat16 g_wdl[(size_t)NE*FF*HID];
__device__ __align__(256) __nv_bfloat16 g_hh[(size_t)NSLOT*FF];
__device__ __align__(256) __nv_bfloat16 g_hl[(size_t)NSLOT*FF];
__device__ __align__(256) float g_dout[(size_t)NSLOT*HID];

// ---------------- helpers ---------------------------------------------------
__device__ __forceinline__ uint32_t smem_u32(const void* p) {
    uint32_t a;
    asm("{ .reg .u64 t; cvta.to.shared.u64 t, %1; cvt.u32.u64 %0, t; }" : "=r"(a) : "l"(p));
    return a;
}
__device__ __forceinline__ void cp16(uint32_t dst, const void* src) {
    asm volatile("cp.async.cg.shared.global [%0], [%1], 16;"
        :: "r"(dst), "l"(__cvta_generic_to_global(src)) : "memory");
}
#define CP_COMMIT() asm volatile("cp.async.commit_group;" ::: "memory")
#define CP_WAIT1()  asm volatile("cp.async.wait_group 1;" ::: "memory")
#define CP_WAIT0()  asm volatile("cp.async.wait_group 0;" ::: "memory")

__device__ __forceinline__ void ldsm4(uint32_t* r, uint32_t addr) {
    asm volatile("ldmatrix.sync.aligned.m8n8.x4.shared.b16 {%0,%1,%2,%3}, [%4];"
        : "=r"(r[0]), "=r"(r[1]), "=r"(r[2]), "=r"(r[3]) : "r"(addr));
}
__device__ __forceinline__ void ldsm4t(uint32_t* r, uint32_t addr) {
    asm volatile("ldmatrix.sync.aligned.m8n8.x4.trans.shared.b16 {%0,%1,%2,%3}, [%4];"
        : "=r"(r[0]), "=r"(r[1]), "=r"(r[2]), "=r"(r[3]) : "r"(addr));
}
__device__ __forceinline__ void mma16816(float* d, const uint32_t* a, const uint32_t* b) {
    asm volatile("mma.sync.aligned.m16n8k16.row.col.f32.bf16.bf16.f32 "
        "{%0,%1,%2,%3}, {%4,%5,%6,%7}, {%8,%9}, {%0,%1,%2,%3};"
        : "+f"(d[0]), "+f"(d[1]), "+f"(d[2]), "+f"(d[3])
        : "r"(a[0]), "r"(a[1]), "r"(a[2]), "r"(a[3]), "r"(b[0]), "r"(b[1]));
}
__device__ __forceinline__ uint32_t pack_bf16(float a, float b) {
    unsigned short lo = __bfloat16_as_ushort(__float2bfloat16_rn(a));
    unsigned short hi = __bfloat16_as_ushort(__float2bfloat16_rn(b));
    return (uint32_t)lo | ((uint32_t)hi << 16);
}

// SMEM tile strides (bytes): conflict-free for ldmatrix
#define A_STRIDE 80     // 64B data (32 bf16) + 16B pad
#define B_STRIDE 144    // 128B data (64 bf16) + 16B pad

#define A_PLANE (BM*A_STRIDE)              // 10240
#define B_PLANE (KC*B_STRIDE)              // 4608
#define G1_STAGE (2*A_PLANE + 4*B_PLANE)   // 38912
#define G2_STAGE (2*A_PLANE + 2*B_PLANE)   // 29696
#define G1_SMEM  (2*G1_STAGE)              // 77824
#define G2_SMEM  (2*G2_STAGE)              // 59392

// ---------------- split convert: dst selected ON DEVICE ---------------------
__global__ void split_kernel(const float* __restrict__ src, int which)
{
    __nv_bfloat16* dh; __nv_bfloat16* dl;
    switch (which) {
        case 0:  dh = g_xh;  dl = g_xl;  break;
        case 1:  dh = g_wgh; dl = g_wgl; break;
        case 2:  dh = g_wuh; dl = g_wul; break;
        default: dh = g_wdh; dl = g_wdl; break;
    }
    size_t i = (size_t)blockIdx.x * blockDim.x + threadIdx.x;   // float4 index
    float4 v = *(const float4*)(src + i * 4);
    float h0 = __bfloat162float(__float2bfloat16_rn(v.x));
    float h1 = __bfloat162float(__float2bfloat16_rn(v.y));
    float h2 = __bfloat162float(__float2bfloat16_rn(v.z));
    float h3 = __bfloat162float(__float2bfloat16_rn(v.w));
    *(uint2*)(dh + i*4) = make_uint2(pack_bf16(v.x, v.y), pack_bf16(v.z, v.w));
    *(uint2*)(dl + i*4) = make_uint2(pack_bf16(v.x - h0, v.y - h1), pack_bf16(v.z - h2, v.w - h3));
}

// ---------------- router ----------------------------------------------------
__global__ void router_kernel(const float* __restrict__ x, const float* __restrict__ gw)
{
    int wid  = (blockIdx.x * blockDim.x + threadIdx.x) >> 5;
    int lane = threadIdx.x & 31;
    if (wid >= NT) return;
    const float* xr = x + (size_t)wid * HID;
    float acc[NE];
    #pragma unroll
    for (int e = 0; e < NE; e++) acc[e] = 0.f;
    for (int h = lane; h < HID; h += 32) {
        float  xv = xr[h];
        float4 a  = *(const float4*)(gw + h*NE);
        float4 b  = *(const float4*)(gw + h*NE + 4);
        acc[0] += xv*a.x; acc[1] += xv*a.y; acc[2] += xv*a.z; acc[3] += xv*a.w;
        acc[4] += xv*b.x; acc[5] += xv*b.y; acc[6] += xv*b.z; acc[7] += xv*b.w;
    }
    #pragma unroll
    for (int e = 0; e < NE; e++)
        #pragma unroll
        for (int o = 16; o > 0; o >>= 1)
            acc[e] += __shfl_xor_sync(0xffffffffu, acc[e], o);
    if (lane == 0) {
        float m = acc[0];
        #pragma unroll
        for (int e = 1; e < NE; e++) m = fmaxf(m, acc[e]);
        float p[NE], s = 0.f;
        #pragma unroll
        for (int e = 0; e < NE; e++) { p[e] = expf(acc[e] - m); s += p[e]; }
        float inv = 1.f / s;
        #pragma unroll
        for (int e = 0; e < NE; e++) p[e] *= inv;
        int i0 = 0;
        #pragma unroll
        for (int e = 1; e < NE; e++) if (p[e] > p[i0]) i0 = e;
        int i1 = (i0 == 0) ? 1 : 0;
        #pragma unroll
        for (int e = 0; e < NE; e++) if (e != i0 && p[e] > p[i1]) i1 = e;
        float w0 = 1.f / (1.f + expf(p[i1] - p[i0]));
        g_top_i[wid*2]   = i0;  g_top_i[wid*2+1] = i1;
        g_top_w[wid*2]   = w0;  g_top_w[wid*2+1] = 1.f - w0;
    }
}

// ---------------- routing build (deterministic) ------------------------------
__global__ void route_build_kernel()
{
    __shared__ int counts[NE];
    __shared__ int offsets[NE+1];
    const int tid  = threadIdx.x;
    const int warp = tid >> 5;
    const int lane = tid & 31;
    int c = 0;
    for (int p = lane; p < NSLOT; p += 32)
        if (g_top_i[p] == warp) c++;
    #pragma unroll
    for (int o = 16; o > 0; o >>= 1) c += __shfl_down_sync(0xffffffffu, c, o);
    if (lane == 0) counts[warp] = c;
    __syncthreads();
    if (tid == 0) {
        int s = 0;
        for (int e = 0; e < NE; e++) { offsets[e] = s; s += counts[e]; }
        offsets[NE] = s;
    }
    __syncthreads();
    int base = offsets[warp];
    for (int p0 = 0; p0 < NSLOT; p0 += 32) {
        int p = p0 + lane;
        bool f = (g_top_i[p] == warp);
        unsigned msk = __ballot_sync(0xffffffffu, f);
        if (f) {
            int slot = base + __popc(msk & ((1u << lane) - 1u));
            g_slot_token[slot] = p >> 1;
            g_token_slot[p]    = slot;
        }
        base += __popc(msk);
    }
    __syncthreads();
    if (tid == 0) {
        int nt = 0;
        for (int e = 0; e < NE; e++) {
            int cnt = counts[e];
            for (int r = 0; r < cnt; r += BM) {
                g_tile_e[nt] = e;
                g_tile_row0[nt] = offsets[e] + r;
                g_tile_nrows[nt] = min(BM, cnt - r);
                nt++;
            }
        }
        g_num_tiles = nt;
    }
}

// ---------------- GEMM1: pipelined mma.sync bf16x3, gate+up + SwiGLU --------
__global__ void __launch_bounds__(256) gemm1_kernel()
{
    const int tile = blockIdx.x;
    if (tile >= g_num_tiles) return;
    const int e     = g_tile_e[tile];
    const int row0  = g_tile_row0[tile];
    const int nrows = g_tile_nrows[tile];
    const int n0    = blockIdx.y * BN;

    extern __shared__ __align__(16) char sm[];
    __shared__ int stok[BM];

    const int tid = threadIdx.x, lane = tid & 31, wid = tid >> 5;
    const int warpM = wid & 3, warpN = wid >> 2;

    if (tid < BM) stok[tid] = (tid < nrows) ? g_slot_token[row0 + tid] : 0;
    __syncthreads();

    const __nv_bfloat16* bsrc[4] = {
        g_wgh + (size_t)e*HID*FF, g_wgl + (size_t)e*HID*FF,
        g_wuh + (size_t)e*HID*FF, g_wul + (size_t)e*HID*FF };

    const uint32_t sb = smem_u32(sm);

    float ag[2][4][4], au[2][4][4];
    #pragma unroll
    for (int i = 0; i < 2; i++)
        #pragma unroll
        for (int g = 0; g < 4; g++)
            #pragma unroll
            for (int r = 0; r < 4; r++) { ag[i][g][r] = 0.f; au[i][g][r] = 0.f; }

    auto load_chunk = [&](int ch, int buf) {
        const uint32_t st = sb + buf * G1_STAGE;
        const int k0 = ch * KC;
        #pragma unroll
        for (int p = 0; p < 2; p++) {
            const __nv_bfloat16* xs = p ? g_xl : g_xh;
            #pragma unroll
            for (int t = 0; t < 2; t++) {
                int idx = tid + t*256;
                int row = idx >> 2, seg = idx & 3;
                cp16(st + p*A_PLANE + row*A_STRIDE + seg*16,
                     xs + (size_t)stok[row]*HID + k0 + seg*8);
            }
        }
        {
            int row = tid >> 3, seg = tid & 7;
            #pragma unroll
            for (int p = 0; p < 4; p++)
                cp16(st + 2*A_PLANE + p*B_PLANE + row*B_STRIDE + seg*16,
                     bsrc[p] + (size_t)(k0+row)*FF + n0 + seg*8);
        }
        CP_COMMIT();
    };

    const int NCH = HID / KC;     // 32
    load_chunk(0, 0);

    for (int ch = 0; ch < NCH; ch++) {
        if (ch + 1 < NCH) { load_chunk(ch + 1, (ch + 1) & 1); CP_WAIT1(); }
        else              { CP_WAIT0(); }
        __syncthreads();

        const uint32_t st = sb + (ch & 1) * G1_STAGE;
        #pragma unroll
        for (int kk = 0; kk < 2; kk++) {
            uint32_t af[2][2][4];     // [plane][i]
            #pragma unroll
            for (int i = 0; i < 2; i++) {
                uint32_t ar = (uint32_t)(warpM*32 + i*16 + (lane & 15))*A_STRIDE
                              + kk*32 + (lane >> 4)*16;
                ldsm4(af[0][i], st + ar);
                ldsm4(af[1][i], st + A_PLANE + ar);
            }
            uint32_t br = (uint32_t)(kk*16 + (lane & 15))*B_STRIDE
                          + warpN*64 + (lane >> 4)*16;
            uint32_t bf[4][4][2];     // [plane][ngroup]
            #pragma unroll
            for (int p = 0; p < 4; p++) {
                uint32_t q0[4], q1[4];
                ldsm4t(q0, st + 2*A_PLANE + p*B_PLANE + br);
                ldsm4t(q1, st + 2*A_PLANE + p*B_PLANE + br + 32);
                bf[p][0][0]=q0[0]; bf[p][0][1]=q0[1];
                bf[p][1][0]=q0[2]; bf[p][1][1]=q0[3];
                bf[p][2][0]=q1[0]; bf[p][2][1]=q1[1];
                bf[p][3][0]=q1[2]; bf[p][3][1]=q1[3];
            }
            #pragma unroll
            for (int i = 0; i < 2; i++)
                #pragma unroll
                for (int g = 0; g < 4; g++) {
                    mma16816(ag[i][g], af[0][i], bf[0][g]);
                    mma16816(ag[i][g], af[0][i], bf[1][g]);
                    mma16816(ag[i][g], af[1][i], bf[0][g]);
                    mma16816(au[i][g], af[0][i], bf[2][g]);
                    mma16816(au[i][g], af[0][i], bf[3][g]);
                    mma16816(au[i][g], af[1][i], bf[2][g]);
                }
        }
        __syncthreads();
    }

    const int qr = lane >> 2;
    const int qc = 2 * (lane & 3);
    #pragma unroll
    for (int i = 0; i < 2; i++)
        #pragma unroll
        for (int g = 0; g < 4; g++) {
            int col = n0 + warpN*32 + g*8 + qc;
            #pragma unroll
            for (int half = 0; half < 2; half++) {
                int tm = warpM*32 + i*16 + qr + half*8;
                if (tm < nrows) {
                    float g0 = ag[i][g][half*2],   u0 = au[i][g][half*2];
                    float g1 = ag[i][g][half*2+1], u1 = au[i][g][half*2+1];
                    float v0 = (g0 / (1.f + __expf(-g0))) * u0;
                    float v1 = (g1 / (1.f + __expf(-g1))) * u1;
                    float hh0 = __bfloat162float(__float2bfloat16_rn(v0));
                    float hh1 = __bfloat162float(__float2bfloat16_rn(v1));
                    size_t off = (size_t)(row0 + tm) * FF + col;
                    *(uint32_t*)(g_hh + off) = pack_bf16(v0, v1);
                    *(uint32_t*)(g_hl + off) = pack_bf16(v0 - hh0, v1 - hh1);
                }
            }
        }
}

// ---------------- GEMM2: pipelined mma.sync bf16x3, down-proj ---------------
__global__ void __launch_bounds__(256) gemm2_kernel()
{
    const int tile = blockIdx.x;
    if (tile >= g_num_tiles) return;
    const int e     = g_tile_e[tile];
    const int row0  = g_tile_row0[tile];
    const int nrows = g_tile_nrows[tile];
    const int n0    = blockIdx.y * BN;

    extern __shared__ __align__(16) char sm[];

    const int tid = threadIdx.x, lane = tid & 31, wid = tid >> 5;
    const int warpM = wid & 3, warpN = wid >> 2;

    const __nv_bfloat16* bsrc[2] = {
        g_wdh + (size_t)e*FF*HID, g_wdl + (size_t)e*FF*HID };

    const uint32_t sb = smem_u32(sm);

    float acc[2][4][4];
    #pragma unroll
    for (int i = 0; i < 2; i++)
        #pragma unroll
        for (int g = 0; g < 4; g++)
            #pragma unroll
            for (int r = 0; r < 4; r++) acc[i][g][r] = 0.f;

    auto load_chunk = [&](int ch, int buf) {
        const uint32_t st = sb + buf * G2_STAGE;
        const int k0 = ch * KC;
        #pragma unroll
        for (int p = 0; p < 2; p++) {
            const __nv_bfloat16* hs = p ? g_hl : g_hh;
            #pragma unroll
            for (int t = 0; t < 2; t++) {
                int idx = tid + t*256;
                int row = idx >> 2, seg = idx & 3;
                int r = row0 + row; if (r > NSLOT-1) r = NSLOT-1;
                cp16(st + p*A_PLANE + row*A_STRIDE + seg*16,
                     hs + (size_t)r*FF + k0 + seg*8);
            }
        }
        {
            int row = tid >> 3, seg = tid & 7;
            #pragma unroll
            for (int p = 0; p < 2; p++)
                cp16(st + 2*A_PLANE + p*B_PLANE + row*B_STRIDE + seg*16,
                     bsrc[p] + (size_t)(k0+row)*HID + n0 + seg*8);
        }
        CP_COMMIT();
    };

    const int NCH = FF / KC;     // 128
    load_chunk(0, 0);

    for (int ch = 0; ch < NCH; ch++) {
        if (ch + 1 < NCH) { load_chunk(ch + 1, (ch + 1) & 1); CP_WAIT1(); }
        else              { CP_WAIT0(); }
        __syncthreads();

        const uint32_t st = sb + (ch & 1) * G2_STAGE;
        #pragma unroll
        for (int kk = 0; kk < 2; kk++) {
            uint32_t af[2][2][4];
            #pragma unroll
            for (int i = 0; i < 2; i++) {
                uint32_t ar = (uint32_t)(warpM*32 + i*16 + (lane & 15))*A_STRIDE
                              + kk*32 + (lane >> 4)*16;
                ldsm4(af[0][i], st + ar);
                ldsm4(af[1][i], st + A_PLANE + ar);
            }
            uint32_t br = (uint32_t)(kk*16 + (lane & 15))*B_STRIDE
                          + warpN*64 + (lane >> 4)*16;
            uint32_t bf[2][4][2];
            #pragma unroll
            for (int p = 0; p < 2; p++) {
                uint32_t q0[4], q1[4];
                ldsm4t(q0, st + 2*A_PLANE + p*B_PLANE + br);
                ldsm4t(q1, st + 2*A_PLANE + p*B_PLANE + br + 32);
                bf[p][0][0]=q0[0]; bf[p][0][1]=q0[1];
                bf[p][1][0]=q0[2]; bf[p][1][1]=q0[3];
                bf[p][2][0]=q1[0]; bf[p][2][1]=q1[1];
                bf[p][3][0]=q1[2]; bf[p][3][1]=q1[3];
            }
            #pragma unroll
            for (int i = 0; i < 2; i++)
                #pragma unroll
                for (int g = 0; g < 4; g++) {
                    mma16816(acc[i][g], af[0][i], bf[0][g]);
                    mma16816(acc[i][g], af[0][i], bf[1][g]);
                    mma16816(acc[i][g], af[1][i], bf[0][g]);
                }
        }
        __syncthreads();
    }

    const int qr = lane >> 2;
    const int qc = 2 * (lane & 3);
    #pragma unroll
    for (int i = 0; i < 2; i++)
        #pragma unroll
        for (int g = 0; g < 4; g++) {
            int col = n0 + warpN*32 + g*8 + qc;
            #pragma unroll
            for (int half = 0; half < 2; half++) {
                int tm = warpM*32 + i*16 + qr + half*8;
                if (tm < nrows) {
                    float2 v = make_float2(acc[i][g][half*2], acc[i][g][half*2+1]);
                    *(float2*)(g_dout + (size_t)(row0 + tm)*HID + col) = v;
                }
            }
        }
}

// ---------------- combine ----------------------------------------------------
__global__ void combine_kernel(float* __restrict__ out)
{
    const int t  = blockIdx.x;
    const int s0 = g_token_slot[t*2];
    const int s1 = g_token_slot[t*2+1];
    const float w0 = g_top_w[t*2];
    const float w1 = g_top_w[t*2+1];
    const int h = threadIdx.x << 2;
    float4 d0 = *(const float4*)(g_dout + (size_t)s0*HID + h);
    float4 d1 = *(const float4*)(g_dout + (size_t)s1*HID + h);
    float4 o;
    o.x = w0*d0.x + w1*d1.x;
    o.y = w0*d0.y + w1*d1.y;
    o.z = w0*d0.z + w1*d1.z;
    o.w = w0*d0.w + w1*d1.w;
    *(float4*)(out + (size_t)t*HID + h) = o;
}

// ---------------------------------------------------------------------------
extern "C" void kernel_launch(void* const* d_in, const int* in_sizes, int n_in,
                              void* d_out, int out_size)
{
    const float* x      = (const float*)d_in[0];
    const float* gate_w = (const float*)d_in[1];
    const float* w_gate = (const float*)d_in[2];
    const float* w_up   = (const float*)d_in[3];
    const float* w_down = (const float*)d_in[4];
    float* out = (float*)d_out;

    static int attr_done = 0;
    if (!attr_done) {
        cudaFuncSetAttribute(gemm1_kernel, cudaFuncAttributeMaxDynamicSharedMemorySize, G1_SMEM);
        cudaFuncSetAttribute(gemm2_kernel, cudaFuncAttributeMaxDynamicSharedMemorySize, G2_SMEM);
        attr_done = 1;
    }

    router_kernel<<<NT*32/256, 256>>>(x, gate_w);
    route_build_kernel<<<1, 256>>>();
    split_kernel<<<(NT*HID/4)/256, 256>>>(x, 0);
    split_kernel<<<(NE*HID*FF/4)/256, 256>>>(w_gate, 1);
    split_kernel<<<(NE*HID*FF/4)/256, 256>>>(w_up,   2);
    split_kernel<<<(NE*FF*HID/4)/256, 256>>>(w_down, 3);
    dim3 g1(MAX_TILES, FF/BN);    // 40 x 64
    gemm1_kernel<<<g1, 256, G1_SMEM>>>();
    dim3 g2(MAX_TILES, HID/BN);   // 40 x 16
    gemm2_kernel<<<g2, 256, G2_SMEM>>>();
    combine_kernel<<<NT, 256>>>(out);
}

// round 10
// speedup vs baseline: 1.1429x; 1.1429x over previous
#include <cuda_runtime.h>
#include <cuda_bf16.h>
#include <math.h>
#include <stdint.h>

#define HID   1024
#define FF    4096
#define NE    8
#define NT    2048
#define NSLOT (NT*2)
#define BM    128
#define BN    64
#define KC    32
#define MAX_TILES 40

// ---------------- scratch (static device globals; no allocation) ------------
__device__ __align__(256) int   g_top_i[NT*2];
__device__ __align__(256) float g_top_w[NT*2];
__device__ __align__(256) int   g_slot_token[NSLOT];
__device__ __align__(256) int   g_token_slot[NT*2];
__device__ __align__(256) int   g_tile_e[MAX_TILES];
__device__ __align__(256) int   g_tile_row0[MAX_TILES];
__device__ __align__(256) int   g_tile_nrows[MAX_TILES];
__device__ int   g_num_tiles;

// bf16 hi/lo planes, native layouts
__device__ __align__(256) __nv_bfloat16 g_xh[NT*HID];
__device__ __align__(256) __nv_bfloat16 g_xl[NT*HID];
__device__ __align__(256) __nv_bfloat16 g_wgh[(size_t)NE*HID*FF];
__device__ __align__(256) __nv_bfloat16 g_wgl[(size_t)NE*HID*FF];
__device__ __align__(256) __nv_bfloat16 g_wuh[(size_t)NE*HID*FF];
__device__ __align__(256) __nv_bfloat16 g_wul[(size_t)NE*HID*FF];
__device__ __align__(256) __nv_bfloat16 g_wdh[(size_t)NE*FF*HID];
__device__ __align__(256) __nv_bfloat16 g_wdl[(size_t)NE*FF*HID];
__device__ __align__(256) __nv_bfloat16 g_hh[(size_t)NSLOT*FF];
__device__ __align__(256) __nv_bfloat16 g_hl[(size_t)NSLOT*FF];
__device__ __align__(256) float g_dout[(size_t)NSLOT*HID];

// ---------------- helpers ---------------------------------------------------
__device__ __forceinline__ uint32_t smem_u32(const void* p) {
    uint32_t a;
    asm("{ .reg .u64 t; cvta.to.shared.u64 t, %1; cvt.u32.u64 %0, t; }" : "=r"(a) : "l"(p));
    return a;
}
__device__ __forceinline__ void cp16(uint32_t dst, const void* src) {
    asm volatile("cp.async.cg.shared.global [%0], [%1], 16;"
        :: "r"(dst), "l"(__cvta_generic_to_global(src)) : "memory");
}
#define CP_COMMIT() asm volatile("cp.async.commit_group;" ::: "memory")
#define CP_WAIT0()  asm volatile("cp.async.wait_group 0;" ::: "memory")

__device__ __forceinline__ void ldsm4(uint32_t* r, uint32_t addr) {
    asm volatile("ldmatrix.sync.aligned.m8n8.x4.shared.b16 {%0,%1,%2,%3}, [%4];"
        : "=r"(r[0]), "=r"(r[1]), "=r"(r[2]), "=r"(r[3]) : "r"(addr));
}
__device__ __forceinline__ void ldsm4t(uint32_t* r, uint32_t addr) {
    asm volatile("ldmatrix.sync.aligned.m8n8.x4.trans.shared.b16 {%0,%1,%2,%3}, [%4];"
        : "=r"(r[0]), "=r"(r[1]), "=r"(r[2]), "=r"(r[3]) : "r"(addr));
}
__device__ __forceinline__ void mma16816(float* d, const uint32_t* a, const uint32_t* b) {
    asm volatile("mma.sync.aligned.m16n8k16.row.col.f32.bf16.bf16.f32 "
        "{%0,%1,%2,%3}, {%4,%5,%6,%7}, {%8,%9}, {%0,%1,%2,%3};"
        : "+f"(d[0]), "+f"(d[1]), "+f"(d[2]), "+f"(d[3])
        : "r"(a[0]), "r"(a[1]), "r"(a[2]), "r"(a[3]), "r"(b[0]), "r"(b[1]));
}
__device__ __forceinline__ uint32_t pack_bf16(float a, float b) {
    unsigned short lo = __bfloat16_as_ushort(__float2bfloat16_rn(a));
    unsigned short hi = __bfloat16_as_ushort(__float2bfloat16_rn(b));
    return (uint32_t)lo | ((uint32_t)hi << 16);
}

// SMEM tile strides (bytes): conflict-free for ldmatrix
#define A_STRIDE 80     // 64B data (32 bf16) + 16B pad
#define B_STRIDE 144    // 128B data (64 bf16) + 16B pad
// GEMM2 wide-B tile: 128 bf16 = 256B data + 16B pad
#define B2_STRIDE 272

// ---------------- split convert: dst selected ON DEVICE ---------------------
__global__ void split_kernel(const float* __restrict__ src, int which)
{
    __nv_bfloat16* dh; __nv_bfloat16* dl;
    switch (which) {
        case 0:  dh = g_xh;  dl = g_xl;  break;
        case 1:  dh = g_wgh; dl = g_wgl; break;
        case 2:  dh = g_wuh; dl = g_wul; break;
        default: dh = g_wdh; dl = g_wdl; break;
    }
    size_t i = (size_t)blockIdx.x * blockDim.x + threadIdx.x;   // float4 index
    float4 v = *(const float4*)(src + i * 4);
    float h0 = __bfloat162float(__float2bfloat16_rn(v.x));
    float h1 = __bfloat162float(__float2bfloat16_rn(v.y));
    float h2 = __bfloat162float(__float2bfloat16_rn(v.z));
    float h3 = __bfloat162float(__float2bfloat16_rn(v.w));
    *(uint2*)(dh + i*4) = make_uint2(pack_bf16(v.x, v.y), pack_bf16(v.z, v.w));
    *(uint2*)(dl + i*4) = make_uint2(pack_bf16(v.x - h0, v.y - h1), pack_bf16(v.z - h2, v.w - h3));
}

// ---------------- router ----------------------------------------------------
__global__ void router_kernel(const float* __restrict__ x, const float* __restrict__ gw)
{
    int wid  = (blockIdx.x * blockDim.x + threadIdx.x) >> 5;
    int lane = threadIdx.x & 31;
    if (wid >= NT) return;
    const float* xr = x + (size_t)wid * HID;
    float acc[NE];
    #pragma unroll
    for (int e = 0; e < NE; e++) acc[e] = 0.f;
    for (int h = lane; h < HID; h += 32) {
        float  xv = xr[h];
        float4 a  = *(const float4*)(gw + h*NE);
        float4 b  = *(const float4*)(gw + h*NE + 4);
        acc[0] += xv*a.x; acc[1] += xv*a.y; acc[2] += xv*a.z; acc[3] += xv*a.w;
        acc[4] += xv*b.x; acc[5] += xv*b.y; acc[6] += xv*b.z; acc[7] += xv*b.w;
    }
    #pragma unroll
    for (int e = 0; e < NE; e++)
        #pragma unroll
        for (int o = 16; o > 0; o >>= 1)
            acc[e] += __shfl_xor_sync(0xffffffffu, acc[e], o);
    if (lane == 0) {
        float m = acc[0];
        #pragma unroll
        for (int e = 1; e < NE; e++) m = fmaxf(m, acc[e]);
        float p[NE], s = 0.f;
        #pragma unroll
        for (int e = 0; e < NE; e++) { p[e] = expf(acc[e] - m); s += p[e]; }
        float inv = 1.f / s;
        #pragma unroll
        for (int e = 0; e < NE; e++) p[e] *= inv;
        int i0 = 0;
        #pragma unroll
        for (int e = 1; e < NE; e++) if (p[e] > p[i0]) i0 = e;
        int i1 = (i0 == 0) ? 1 : 0;
        #pragma unroll
        for (int e = 0; e < NE; e++) if (e != i0 && p[e] > p[i1]) i1 = e;
        float w0 = 1.f / (1.f + expf(p[i1] - p[i0]));
        g_top_i[wid*2]   = i0;  g_top_i[wid*2+1] = i1;
        g_top_w[wid*2]   = w0;  g_top_w[wid*2+1] = 1.f - w0;
    }
}

// ---------------- routing build (deterministic) ------------------------------
__global__ void route_build_kernel()
{
    __shared__ int counts[NE];
    __shared__ int offsets[NE+1];
    const int tid  = threadIdx.x;
    const int warp = tid >> 5;
    const int lane = tid & 31;
    int c = 0;
    for (int p = lane; p < NSLOT; p += 32)
        if (g_top_i[p] == warp) c++;
    #pragma unroll
    for (int o = 16; o > 0; o >>= 1) c += __shfl_down_sync(0xffffffffu, c, o);
    if (lane == 0) counts[warp] = c;
    __syncthreads();
    if (tid == 0) {
        int s = 0;
        for (int e = 0; e < NE; e++) { offsets[e] = s; s += counts[e]; }
        offsets[NE] = s;
    }
    __syncthreads();
    int base = offsets[warp];
    for (int p0 = 0; p0 < NSLOT; p0 += 32) {
        int p = p0 + lane;
        bool f = (g_top_i[p] == warp);
        unsigned msk = __ballot_sync(0xffffffffu, f);
        if (f) {
            int slot = base + __popc(msk & ((1u << lane) - 1u));
            g_slot_token[slot] = p >> 1;
            g_token_slot[p]    = slot;
        }
        base += __popc(msk);
    }
    __syncthreads();
    if (tid == 0) {
        int nt = 0;
        for (int e = 0; e < NE; e++) {
            int cnt = counts[e];
            for (int r = 0; r < cnt; r += BM) {
                g_tile_e[nt] = e;
                g_tile_row0[nt] = offsets[e] + r;
                g_tile_nrows[nt] = min(BM, cnt - r);
                nt++;
            }
        }
        g_num_tiles = nt;
    }
}

// ---------------- GEMM1: mma.sync bf16x3, gate+up, fused SwiGLU (R7) --------
__global__ void __launch_bounds__(256) gemm1_kernel()
{
    const int tile = blockIdx.x;
    if (tile >= g_num_tiles) return;
    const int e     = g_tile_e[tile];
    const int row0  = g_tile_row0[tile];
    const int nrows = g_tile_nrows[tile];
    const int n0    = blockIdx.y * BN;

    __shared__ __align__(16) char smA[2][BM*A_STRIDE];     // 2 x 10240
    __shared__ __align__(16) char smB[4][KC*B_STRIDE];     // 4 x 4608
    __shared__ int stok[BM];

    const int tid = threadIdx.x, lane = tid & 31, wid = tid >> 5;
    const int warpM = wid & 3, warpN = wid >> 2;

    if (tid < BM) stok[tid] = (tid < nrows) ? g_slot_token[row0 + tid] : 0;
    __syncthreads();

    const __nv_bfloat16* bsrc[4] = {
        g_wgh + (size_t)e*HID*FF, g_wgl + (size_t)e*HID*FF,
        g_wuh + (size_t)e*HID*FF, g_wul + (size_t)e*HID*FF };

    const uint32_t sa = smem_u32(smA);
    const uint32_t sbb = smem_u32(smB);

    float ag[2][4][4], au[2][4][4];
    #pragma unroll
    for (int i = 0; i < 2; i++)
        #pragma unroll
        for (int g = 0; g < 4; g++)
            #pragma unroll
            for (int r = 0; r < 4; r++) { ag[i][g][r] = 0.f; au[i][g][r] = 0.f; }

    for (int ch = 0; ch < HID/KC; ch++) {      // 32 chunks
        const int k0 = ch * KC;
        #pragma unroll
        for (int p = 0; p < 2; p++) {
            const __nv_bfloat16* xs = p ? g_xl : g_xh;
            #pragma unroll
            for (int t = 0; t < 2; t++) {
                int idx = tid + t*256;
                int row = idx >> 2, seg = idx & 3;
                cp16(sa + p*(BM*A_STRIDE) + row*A_STRIDE + seg*16,
                     xs + (size_t)stok[row]*HID + k0 + seg*8);
            }
        }
        {
            int row = tid >> 3, seg = tid & 7;
            #pragma unroll
            for (int p = 0; p < 4; p++)
                cp16(sbb + p*(KC*B_STRIDE) + row*B_STRIDE + seg*16,
                     bsrc[p] + (size_t)(k0+row)*FF + n0 + seg*8);
        }
        CP_COMMIT(); CP_WAIT0();
        __syncthreads();

        #pragma unroll
        for (int kk = 0; kk < 2; kk++) {
            uint32_t af[2][2][4];     // [plane][i]
            #pragma unroll
            for (int i = 0; i < 2; i++) {
                uint32_t ar = (uint32_t)(warpM*32 + i*16 + (lane & 15))*A_STRIDE
                              + kk*32 + (lane >> 4)*16;
                ldsm4(af[0][i], sa + ar);
                ldsm4(af[1][i], sa + BM*A_STRIDE + ar);
            }
            uint32_t br = (uint32_t)(kk*16 + (lane & 15))*B_STRIDE
                          + warpN*64 + (lane >> 4)*16;
            uint32_t bf[4][4][2];     // [plane][ngroup]
            #pragma unroll
            for (int p = 0; p < 4; p++) {
                uint32_t q0[4], q1[4];
                ldsm4t(q0, sbb + p*(KC*B_STRIDE) + br);
                ldsm4t(q1, sbb + p*(KC*B_STRIDE) + br + 32);
                bf[p][0][0]=q0[0]; bf[p][0][1]=q0[1];
                bf[p][1][0]=q0[2]; bf[p][1][1]=q0[3];
                bf[p][2][0]=q1[0]; bf[p][2][1]=q1[1];
                bf[p][3][0]=q1[2]; bf[p][3][1]=q1[3];
            }
            #pragma unroll
            for (int i = 0; i < 2; i++)
                #pragma unroll
                for (int g = 0; g < 4; g++) {
                    mma16816(ag[i][g], af[0][i], bf[0][g]);
                    mma16816(ag[i][g], af[0][i], bf[1][g]);
                    mma16816(ag[i][g], af[1][i], bf[0][g]);
                    mma16816(au[i][g], af[0][i], bf[2][g]);
                    mma16816(au[i][g], af[0][i], bf[3][g]);
                    mma16816(au[i][g], af[1][i], bf[2][g]);
                }
        }
        __syncthreads();
    }

    const int qr = lane >> 2;
    const int qc = 2 * (lane & 3);
    #pragma unroll
    for (int i = 0; i < 2; i++)
        #pragma unroll
        for (int g = 0; g < 4; g++) {
            int col = n0 + warpN*32 + g*8 + qc;
            #pragma unroll
            for (int half = 0; half < 2; half++) {
                int tm = warpM*32 + i*16 + qr + half*8;
                if (tm < nrows) {
                    float g0 = ag[i][g][half*2],   u0 = au[i][g][half*2];
                    float g1 = ag[i][g][half*2+1], u1 = au[i][g][half*2+1];
                    float v0 = (g0 / (1.f + __expf(-g0))) * u0;
                    float v1 = (g1 / (1.f + __expf(-g1))) * u1;
                    float hh0 = __bfloat162float(__float2bfloat16_rn(v0));
                    float hh1 = __bfloat162float(__float2bfloat16_rn(v1));
                    size_t off = (size_t)(row0 + tm) * FF + col;
                    *(uint32_t*)(g_hh + off) = pack_bf16(v0, v1);
                    *(uint32_t*)(g_hl + off) = pack_bf16(v0 - hh0, v1 - hh1);
                }
            }
        }
}

// ---------------- GEMM2: mma.sync bf16x3, down-proj, BN=128 -----------------
#define BN2 128
__global__ void __launch_bounds__(256) gemm2_kernel()
{
    const int tile = blockIdx.x;
    if (tile >= g_num_tiles) return;
    const int e     = g_tile_e[tile];
    const int row0  = g_tile_row0[tile];
    const int nrows = g_tile_nrows[tile];
    const int n0    = blockIdx.y * BN2;

    __shared__ __align__(16) char smA[2][BM*A_STRIDE];     // 2 x 10240
    __shared__ __align__(16) char smB[2][KC*B2_STRIDE];    // 2 x 8704

    const int tid = threadIdx.x, lane = tid & 31, wid = tid >> 5;
    const int warpM = wid & 3, warpN = wid >> 2;           // warpN covers 64 cols

    const __nv_bfloat16* bsrc[2] = {
        g_wdh + (size_t)e*FF*HID, g_wdl + (size_t)e*FF*HID };

    const uint32_t sa = smem_u32(smA);
    const uint32_t sbb = smem_u32(smB);

    float acc[2][8][4];
    #pragma unroll
    for (int i = 0; i < 2; i++)
        #pragma unroll
        for (int g = 0; g < 8; g++)
            #pragma unroll
            for (int r = 0; r < 4; r++) acc[i][g][r] = 0.f;

    for (int ch = 0; ch < FF/KC; ch++) {       // 128 chunks
        const int k0 = ch * KC;
        // A: 2 planes x 128 rows x 4 segs
        #pragma unroll
        for (int p = 0; p < 2; p++) {
            const __nv_bfloat16* hs = p ? g_hl : g_hh;
            #pragma unroll
            for (int t = 0; t < 2; t++) {
                int idx = tid + t*256;
                int row = idx >> 2, seg = idx & 3;
                int r = row0 + row; if (r > NSLOT-1) r = NSLOT-1;
                cp16(sa + p*(BM*A_STRIDE) + row*A_STRIDE + seg*16,
                     hs + (size_t)r*FF + k0 + seg*8);
            }
        }
        // B: 2 planes x 32 k-rows x 16 segs = 1024 cp16
        #pragma unroll
        for (int t = 0; t < 4; t++) {
            int idx = tid + t*256;
            int p = idx >> 9, rem = idx & 511;
            int row = rem >> 4, seg = rem & 15;
            cp16(sbb + p*(KC*B2_STRIDE) + row*B2_STRIDE + seg*16,
                 bsrc[p] + (size_t)(k0+row)*HID + n0 + seg*8);
        }
        CP_COMMIT(); CP_WAIT0();
        __syncthreads();

        #pragma unroll
        for (int kk = 0; kk < 2; kk++) {
            uint32_t af[2][2][4];
            #pragma unroll
            for (int i = 0; i < 2; i++) {
                uint32_t ar = (uint32_t)(warpM*32 + i*16 + (lane & 15))*A_STRIDE
                              + kk*32 + (lane >> 4)*16;
                ldsm4(af[0][i], sa + ar);
                ldsm4(af[1][i], sa + BM*A_STRIDE + ar);
            }
            uint32_t br = (uint32_t)(kk*16 + (lane & 15))*B2_STRIDE
                          + warpN*128 + (lane >> 4)*16;
            uint32_t bf[2][8][2];     // [plane][ngroup of n8]
            #pragma unroll
            for (int p = 0; p < 2; p++) {
                #pragma unroll
                for (int q = 0; q < 4; q++) {
                    uint32_t qq[4];
                    ldsm4t(qq, sbb + p*(KC*B2_STRIDE) + br + q*32);
                    bf[p][2*q  ][0]=qq[0]; bf[p][2*q  ][1]=qq[1];
                    bf[p][2*q+1][0]=qq[2]; bf[p][2*q+1][1]=qq[3];
                }
            }
            #pragma unroll
            for (int i = 0; i < 2; i++)
                #pragma unroll
                for (int g = 0; g < 8; g++) {
                    mma16816(acc[i][g], af[0][i], bf[0][g]);
                    mma16816(acc[i][g], af[0][i], bf[1][g]);
                    mma16816(acc[i][g], af[1][i], bf[0][g]);
                }
        }
        __syncthreads();
    }

    const int qr = lane >> 2;
    const int qc = 2 * (lane & 3);
    #pragma unroll
    for (int i = 0; i < 2; i++)
        #pragma unroll
        for (int g = 0; g < 8; g++) {
            // FIX (R9 bug): byte offset warpN*128 == 64 fp32/bf16 COLUMNS, not 128.
            int col = n0 + warpN*64 + g*8 + qc;
            #pragma unroll
            for (int half = 0; half < 2; half++) {
                int tm = warpM*32 + i*16 + qr + half*8;
                if (tm < nrows) {
                    float2 v = make_float2(acc[i][g][half*2], acc[i][g][half*2+1]);
                    *(float2*)(g_dout + (size_t)(row0 + tm)*HID + col) = v;
                }
            }
        }
}

// ---------------- combine ----------------------------------------------------
__global__ void combine_kernel(float* __restrict__ out)
{
    const int t  = blockIdx.x;
    const int s0 = g_token_slot[t*2];
    const int s1 = g_token_slot[t*2+1];
    const float w0 = g_top_w[t*2];
    const float w1 = g_top_w[t*2+1];
    const int h = threadIdx.x << 2;
    float4 d0 = *(const float4*)(g_dout + (size_t)s0*HID + h);
    float4 d1 = *(const float4*)(g_dout + (size_t)s1*HID + h);
    float4 o;
    o.x = w0*d0.x + w1*d1.x;
    o.y = w0*d0.y + w1*d1.y;
    o.z = w0*d0.z + w1*d1.z;
    o.w = w0*d0.w + w1*d1.w;
    *(float4*)(out + (size_t)t*HID + h) = o;
}

// ---------------------------------------------------------------------------
extern "C" void kernel_launch(void* const* d_in, const int* in_sizes, int n_in,
                              void* d_out, int out_size)
{
    const float* x      = (const float*)d_in[0];
    const float* gate_w = (const float*)d_in[1];
    const float* w_gate = (const float*)d_in[2];
    const float* w_up   = (const float*)d_in[3];
    const float* w_down = (const float*)d_in[4];
    float* out = (float*)d_out;

    router_kernel<<<NT*32/256, 256>>>(x, gate_w);
    route_build_kernel<<<1, 256>>>();
    split_kernel<<<(NT*HID/4)/256, 256>>>(x, 0);
    split_kernel<<<(NE*HID*FF/4)/256, 256>>>(w_gate, 1);
    split_kernel<<<(NE*HID*FF/4)/256, 256>>>(w_up,   2);
    split_kernel<<<(NE*FF*HID/4)/256, 256>>>(w_down, 3);
    dim3 g1(MAX_TILES, FF/BN);     // 40 x 64
    gemm1_kernel<<<g1, 256>>>();
    dim3 g2(MAX_TILES, HID/BN2);   // 40 x 8
    gemm2_kernel<<<g2, 256>>>();
    combine_kernel<<<NT, 256>>>(out);
}

// round 11
// speedup vs baseline: 1.2650x; 1.1068x over previous
#include <cuda_runtime.h>
#include <cuda_fp16.h>
#include <math.h>
#include <stdint.h>

#define HID   1024
#define FF    4096
#define NE    8
#define NT    2048
#define NSLOT (NT*2)
#define BM    128
#define BN    64
#define KC    32
#define MAX_TILES 40

// ---------------- scratch (static device globals; no allocation) ------------
__device__ __align__(256) int   g_top_i[NT*2];
__device__ __align__(256) float g_top_w[NT*2];
__device__ __align__(256) int   g_slot_token[NSLOT];
__device__ __align__(256) int   g_token_slot[NT*2];
__device__ __align__(256) int   g_tile_e[MAX_TILES];
__device__ __align__(256) int   g_tile_row0[MAX_TILES];
__device__ __align__(256) int   g_tile_nrows[MAX_TILES];
__device__ int   g_num_tiles;

// fp16 planes: activations split hi/lo, weights single fp16
__device__ __align__(256) __half g_xh[NT*HID];
__device__ __align__(256) __half g_xl[NT*HID];
__device__ __align__(256) __half g_wg16[(size_t)NE*HID*FF];
__device__ __align__(256) __half g_wu16[(size_t)NE*HID*FF];
__device__ __align__(256) __half g_wd16[(size_t)NE*FF*HID];
__device__ __align__(256) __half g_hh[(size_t)NSLOT*FF];
__device__ __align__(256) __half g_hl[(size_t)NSLOT*FF];
__device__ __align__(256) float g_dout[(size_t)NSLOT*HID];

// ---------------- helpers ---------------------------------------------------
__device__ __forceinline__ uint32_t smem_u32(const void* p) {
    uint32_t a;
    asm("{ .reg .u64 t; cvta.to.shared.u64 t, %1; cvt.u32.u64 %0, t; }" : "=r"(a) : "l"(p));
    return a;
}
__device__ __forceinline__ void cp16(uint32_t dst, const void* src) {
    asm volatile("cp.async.cg.shared.global [%0], [%1], 16;"
        :: "r"(dst), "l"(__cvta_generic_to_global(src)) : "memory");
}
#define CP_COMMIT() asm volatile("cp.async.commit_group;" ::: "memory")
#define CP_WAIT0()  asm volatile("cp.async.wait_group 0;" ::: "memory")

__device__ __forceinline__ void ldsm4(uint32_t* r, uint32_t addr) {
    asm volatile("ldmatrix.sync.aligned.m8n8.x4.shared.b16 {%0,%1,%2,%3}, [%4];"
        : "=r"(r[0]), "=r"(r[1]), "=r"(r[2]), "=r"(r[3]) : "r"(addr));
}
__device__ __forceinline__ void ldsm4t(uint32_t* r, uint32_t addr) {
    asm volatile("ldmatrix.sync.aligned.m8n8.x4.trans.shared.b16 {%0,%1,%2,%3}, [%4];"
        : "=r"(r[0]), "=r"(r[1]), "=r"(r[2]), "=r"(r[3]) : "r"(addr));
}
__device__ __forceinline__ void mma16816(float* d, const uint32_t* a, const uint32_t* b) {
    asm volatile("mma.sync.aligned.m16n8k16.row.col.f32.f16.f16.f32 "
        "{%0,%1,%2,%3}, {%4,%5,%6,%7}, {%8,%9}, {%0,%1,%2,%3};"
        : "+f"(d[0]), "+f"(d[1]), "+f"(d[2]), "+f"(d[3])
        : "r"(a[0]), "r"(a[1]), "r"(a[2]), "r"(a[3]), "r"(b[0]), "r"(b[1]));
}
__device__ __forceinline__ uint32_t pack_h2(float a, float b) {
    unsigned short lo = __half_as_ushort(__float2half_rn(a));
    unsigned short hi = __half_as_ushort(__float2half_rn(b));
    return (uint32_t)lo | ((uint32_t)hi << 16);
}

// SMEM tile strides (bytes): conflict-free for ldmatrix
#define A_STRIDE 80     // 64B data (32 fp16) + 16B pad
#define B_STRIDE 144    // 128B data (64 fp16) + 16B pad
#define B2_STRIDE 272   // 256B data (128 fp16) + 16B pad

// ---------------- converts (dst selected ON DEVICE) -------------------------
__global__ void convert_kernel(const float* __restrict__ src, int which)
{
    size_t i = (size_t)blockIdx.x * blockDim.x + threadIdx.x;   // float4 index
    float4 v = *(const float4*)(src + i * 4);
    if (which == 0) {
        // x: split into fp16 hi + lo
        float h0 = __half2float(__float2half_rn(v.x));
        float h1 = __half2float(__float2half_rn(v.y));
        float h2 = __half2float(__float2half_rn(v.z));
        float h3 = __half2float(__float2half_rn(v.w));
        *(uint2*)(g_xh + i*4) = make_uint2(pack_h2(v.x, v.y), pack_h2(v.z, v.w));
        *(uint2*)(g_xl + i*4) = make_uint2(pack_h2(v.x - h0, v.y - h1), pack_h2(v.z - h2, v.w - h3));
    } else {
        __half* d = (which == 1) ? g_wg16 : (which == 2) ? g_wu16 : g_wd16;
        *(uint2*)(d + i*4) = make_uint2(pack_h2(v.x, v.y), pack_h2(v.z, v.w));
    }
}

// ---------------- router ----------------------------------------------------
__global__ void router_kernel(const float* __restrict__ x, const float* __restrict__ gw)
{
    int wid  = (blockIdx.x * blockDim.x + threadIdx.x) >> 5;
    int lane = threadIdx.x & 31;
    if (wid >= NT) return;
    const float* xr = x + (size_t)wid * HID;
    float acc[NE];
    #pragma unroll
    for (int e = 0; e < NE; e++) acc[e] = 0.f;
    for (int h = lane; h < HID; h += 32) {
        float  xv = xr[h];
        float4 a  = *(const float4*)(gw + h*NE);
        float4 b  = *(const float4*)(gw + h*NE + 4);
        acc[0] += xv*a.x; acc[1] += xv*a.y; acc[2] += xv*a.z; acc[3] += xv*a.w;
        acc[4] += xv*b.x; acc[5] += xv*b.y; acc[6] += xv*b.z; acc[7] += xv*b.w;
    }
    #pragma unroll
    for (int e = 0; e < NE; e++)
        #pragma unroll
        for (int o = 16; o > 0; o >>= 1)
            acc[e] += __shfl_xor_sync(0xffffffffu, acc[e], o);
    if (lane == 0) {
        float m = acc[0];
        #pragma unroll
        for (int e = 1; e < NE; e++) m = fmaxf(m, acc[e]);
        float p[NE], s = 0.f;
        #pragma unroll
        for (int e = 0; e < NE; e++) { p[e] = expf(acc[e] - m); s += p[e]; }
        float inv = 1.f / s;
        #pragma unroll
        for (int e = 0; e < NE; e++) p[e] *= inv;
        int i0 = 0;
        #pragma unroll
        for (int e = 1; e < NE; e++) if (p[e] > p[i0]) i0 = e;
        int i1 = (i0 == 0) ? 1 : 0;
        #pragma unroll
        for (int e = 0; e < NE; e++) if (e != i0 && p[e] > p[i1]) i1 = e;
        float w0 = 1.f / (1.f + expf(p[i1] - p[i0]));
        g_top_i[wid*2]   = i0;  g_top_i[wid*2+1] = i1;
        g_top_w[wid*2]   = w0;  g_top_w[wid*2+1] = 1.f - w0;
    }
}

// ---------------- routing build (deterministic) ------------------------------
__global__ void route_build_kernel()
{
    __shared__ int counts[NE];
    __shared__ int offsets[NE+1];
    const int tid  = threadIdx.x;
    const int warp = tid >> 5;
    const int lane = tid & 31;
    int c = 0;
    for (int p = lane; p < NSLOT; p += 32)
        if (g_top_i[p] == warp) c++;
    #pragma unroll
    for (int o = 16; o > 0; o >>= 1) c += __shfl_down_sync(0xffffffffu, c, o);
    if (lane == 0) counts[warp] = c;
    __syncthreads();
    if (tid == 0) {
        int s = 0;
        for (int e = 0; e < NE; e++) { offsets[e] = s; s += counts[e]; }
        offsets[NE] = s;
    }
    __syncthreads();
    int base = offsets[warp];
    for (int p0 = 0; p0 < NSLOT; p0 += 32) {
        int p = p0 + lane;
        bool f = (g_top_i[p] == warp);
        unsigned msk = __ballot_sync(0xffffffffu, f);
        if (f) {
            int slot = base + __popc(msk & ((1u << lane) - 1u));
            g_slot_token[slot] = p >> 1;
            g_token_slot[p]    = slot;
        }
        base += __popc(msk);
    }
    __syncthreads();
    if (tid == 0) {
        int nt = 0;
        for (int e = 0; e < NE; e++) {
            int cnt = counts[e];
            for (int r = 0; r < cnt; r += BM) {
                g_tile_e[nt] = e;
                g_tile_row0[nt] = offsets[e] + r;
                g_tile_nrows[nt] = min(BM, cnt - r);
                nt++;
            }
        }
        g_num_tiles = nt;
    }
}

// ---------------- GEMM1: fp16x2 (A split, B single), gate+up + SwiGLU -------
__global__ void __launch_bounds__(256) gemm1_kernel()
{
    const int tile = blockIdx.x;
    if (tile >= g_num_tiles) return;
    const int e     = g_tile_e[tile];
    const int row0  = g_tile_row0[tile];
    const int nrows = g_tile_nrows[tile];
    const int n0    = blockIdx.y * BN;

    __shared__ __align__(16) char smA[2][BM*A_STRIDE];     // 2 x 10240
    __shared__ __align__(16) char smB[2][KC*B_STRIDE];     // 2 x 4608 (gate, up)
    __shared__ int stok[BM];

    const int tid = threadIdx.x, lane = tid & 31, wid = tid >> 5;
    const int warpM = wid & 3, warpN = wid >> 2;

    if (tid < BM) stok[tid] = (tid < nrows) ? g_slot_token[row0 + tid] : 0;
    __syncthreads();

    const __half* bsrc[2] = {
        g_wg16 + (size_t)e*HID*FF, g_wu16 + (size_t)e*HID*FF };

    const uint32_t sa = smem_u32(smA);
    const uint32_t sbb = smem_u32(smB);

    float ag[2][4][4], au[2][4][4];
    #pragma unroll
    for (int i = 0; i < 2; i++)
        #pragma unroll
        for (int g = 0; g < 4; g++)
            #pragma unroll
            for (int r = 0; r < 4; r++) { ag[i][g][r] = 0.f; au[i][g][r] = 0.f; }

    for (int ch = 0; ch < HID/KC; ch++) {      // 32 chunks
        const int k0 = ch * KC;
        #pragma unroll
        for (int p = 0; p < 2; p++) {
            const __half* xs = p ? g_xl : g_xh;
            #pragma unroll
            for (int t = 0; t < 2; t++) {
                int idx = tid + t*256;
                int row = idx >> 2, seg = idx & 3;
                cp16(sa + p*(BM*A_STRIDE) + row*A_STRIDE + seg*16,
                     xs + (size_t)stok[row]*HID + k0 + seg*8);
            }
        }
        {
            int row = tid >> 3, seg = tid & 7;
            #pragma unroll
            for (int p = 0; p < 2; p++)
                cp16(sbb + p*(KC*B_STRIDE) + row*B_STRIDE + seg*16,
                     bsrc[p] + (size_t)(k0+row)*FF + n0 + seg*8);
        }
        CP_COMMIT(); CP_WAIT0();
        __syncthreads();

        #pragma unroll
        for (int kk = 0; kk < 2; kk++) {
            uint32_t af[2][2][4];     // [plane][i]
            #pragma unroll
            for (int i = 0; i < 2; i++) {
                uint32_t ar = (uint32_t)(warpM*32 + i*16 + (lane & 15))*A_STRIDE
                              + kk*32 + (lane >> 4)*16;
                ldsm4(af[0][i], sa + ar);
                ldsm4(af[1][i], sa + BM*A_STRIDE + ar);
            }
            uint32_t br = (uint32_t)(kk*16 + (lane & 15))*B_STRIDE
                          + warpN*64 + (lane >> 4)*16;
            uint32_t bf[2][4][2];     // [mat: gate/up][ngroup]
            #pragma unroll
            for (int p = 0; p < 2; p++) {
                uint32_t q0[4], q1[4];
                ldsm4t(q0, sbb + p*(KC*B_STRIDE) + br);
                ldsm4t(q1, sbb + p*(KC*B_STRIDE) + br + 32);
                bf[p][0][0]=q0[0]; bf[p][0][1]=q0[1];
                bf[p][1][0]=q0[2]; bf[p][1][1]=q0[3];
                bf[p][2][0]=q1[0]; bf[p][2][1]=q1[1];
                bf[p][3][0]=q1[2]; bf[p][3][1]=q1[3];
            }
            #pragma unroll
            for (int i = 0; i < 2; i++)
                #pragma unroll
                for (int g = 0; g < 4; g++) {
                    mma16816(ag[i][g], af[0][i], bf[0][g]);
                    mma16816(ag[i][g], af[1][i], bf[0][g]);
                    mma16816(au[i][g], af[0][i], bf[1][g]);
                    mma16816(au[i][g], af[1][i], bf[1][g]);
                }
        }
        __syncthreads();
    }

    const int qr = lane >> 2;
    const int qc = 2 * (lane & 3);
    #pragma unroll
    for (int i = 0; i < 2; i++)
        #pragma unroll
        for (int g = 0; g < 4; g++) {
            int col = n0 + warpN*32 + g*8 + qc;
            #pragma unroll
            for (int half = 0; half < 2; half++) {
                int tm = warpM*32 + i*16 + qr + half*8;
                if (tm < nrows) {
                    float g0 = ag[i][g][half*2],   u0 = au[i][g][half*2];
                    float g1 = ag[i][g][half*2+1], u1 = au[i][g][half*2+1];
                    float v0 = (g0 / (1.f + __expf(-g0))) * u0;
                    float v1 = (g1 / (1.f + __expf(-g1))) * u1;
                    float hh0 = __half2float(__float2half_rn(v0));
                    float hh1 = __half2float(__float2half_rn(v1));
                    size_t off = (size_t)(row0 + tm) * FF + col;
                    *(uint32_t*)(g_hh + off) = pack_h2(v0, v1);
                    *(uint32_t*)(g_hl + off) = pack_h2(v0 - hh0, v1 - hh1);
                }
            }
        }
}

// ---------------- GEMM2: fp16x2 down-proj, BN=128 ---------------------------
#define BN2 128
__global__ void __launch_bounds__(256) gemm2_kernel()
{
    const int tile = blockIdx.x;
    if (tile >= g_num_tiles) return;
    const int e     = g_tile_e[tile];
    const int row0  = g_tile_row0[tile];
    const int nrows = g_tile_nrows[tile];
    const int n0    = blockIdx.y * BN2;

    __shared__ __align__(16) char smA[2][BM*A_STRIDE];     // 2 x 10240
    __shared__ __align__(16) char smB[KC*B2_STRIDE];       // 8704

    const int tid = threadIdx.x, lane = tid & 31, wid = tid >> 5;
    const int warpM = wid & 3, warpN = wid >> 2;           // warpN covers 64 cols

    const __half* bsrc = g_wd16 + (size_t)e*FF*HID;

    const uint32_t sa = smem_u32(smA);
    const uint32_t sbb = smem_u32(smB);

    float acc[2][8][4];
    #pragma unroll
    for (int i = 0; i < 2; i++)
        #pragma unroll
        for (int g = 0; g < 8; g++)
            #pragma unroll
            for (int r = 0; r < 4; r++) acc[i][g][r] = 0.f;

    for (int ch = 0; ch < FF/KC; ch++) {       // 128 chunks
        const int k0 = ch * KC;
        // A: 2 planes x 128 rows x 4 segs
        #pragma unroll
        for (int p = 0; p < 2; p++) {
            const __half* hs = p ? g_hl : g_hh;
            #pragma unroll
            for (int t = 0; t < 2; t++) {
                int idx = tid + t*256;
                int row = idx >> 2, seg = idx & 3;
                int r = row0 + row; if (r > NSLOT-1) r = NSLOT-1;
                cp16(sa + p*(BM*A_STRIDE) + row*A_STRIDE + seg*16,
                     hs + (size_t)r*FF + k0 + seg*8);
            }
        }
        // B: 1 plane x 32 k-rows x 16 segs = 512 cp16
        #pragma unroll
        for (int t = 0; t < 2; t++) {
            int idx = tid + t*256;
            int row = idx >> 4, seg = idx & 15;
            cp16(sbb + row*B2_STRIDE + seg*16,
                 bsrc + (size_t)(k0+row)*HID + n0 + seg*8);
        }
        CP_COMMIT(); CP_WAIT0();
        __syncthreads();

        #pragma unroll
        for (int kk = 0; kk < 2; kk++) {
            uint32_t af[2][2][4];
            #pragma unroll
            for (int i = 0; i < 2; i++) {
                uint32_t ar = (uint32_t)(warpM*32 + i*16 + (lane & 15))*A_STRIDE
                              + kk*32 + (lane >> 4)*16;
                ldsm4(af[0][i], sa + ar);
                ldsm4(af[1][i], sa + BM*A_STRIDE + ar);
            }
            uint32_t br = (uint32_t)(kk*16 + (lane & 15))*B2_STRIDE
                          + warpN*128 + (lane >> 4)*16;
            uint32_t bf[8][2];
            #pragma unroll
            for (int q = 0; q < 4; q++) {
                uint32_t qq[4];
                ldsm4t(qq, sbb + br + q*32);
                bf[2*q  ][0]=qq[0]; bf[2*q  ][1]=qq[1];
                bf[2*q+1][0]=qq[2]; bf[2*q+1][1]=qq[3];
            }
            #pragma unroll
            for (int i = 0; i < 2; i++)
                #pragma unroll
                for (int g = 0; g < 8; g++) {
                    mma16816(acc[i][g], af[0][i], bf[g]);
                    mma16816(acc[i][g], af[1][i], bf[g]);
                }
        }
        __syncthreads();
    }

    const int qr = lane >> 2;
    const int qc = 2 * (lane & 3);
    #pragma unroll
    for (int i = 0; i < 2; i++)
        #pragma unroll
        for (int g = 0; g < 8; g++) {
            int col = n0 + warpN*64 + g*8 + qc;   // byte offset 128 == 64 columns
            #pragma unroll
            for (int half = 0; half < 2; half++) {
                int tm = warpM*32 + i*16 + qr + half*8;
                if (tm < nrows) {
                    float2 v = make_float2(acc[i][g][half*2], acc[i][g][half*2+1]);
                    *(float2*)(g_dout + (size_t)(row0 + tm)*HID + col) = v;
                }
            }
        }
}

// ---------------- combine ----------------------------------------------------
__global__ void combine_kernel(float* __restrict__ out)
{
    const int t  = blockIdx.x;
    const int s0 = g_token_slot[t*2];
    const int s1 = g_token_slot[t*2+1];
    const float w0 = g_top_w[t*2];
    const float w1 = g_top_w[t*2+1];
    const int h = threadIdx.x << 2;
    float4 d0 = *(const float4*)(g_dout + (size_t)s0*HID + h);
    float4 d1 = *(const float4*)(g_dout + (size_t)s1*HID + h);
    float4 o;
    o.x = w0*d0.x + w1*d1.x;
    o.y = w0*d0.y + w1*d1.y;
    o.z = w0*d0.z + w1*d1.z;
    o.w = w0*d0.w + w1*d1.w;
    *(float4*)(out + (size_t)t*HID + h) = o;
}

// ---------------------------------------------------------------------------
extern "C" void kernel_launch(void* const* d_in, const int* in_sizes, int n_in,
                              void* d_out, int out_size)
{
    const float* x      = (const float*)d_in[0];
    const float* gate_w = (const float*)d_in[1];
    const float* w_gate = (const float*)d_in[2];
    const float* w_up   = (const float*)d_in[3];
    const float* w_down = (const float*)d_in[4];
    float* out = (float*)d_out;

    router_kernel<<<NT*32/256, 256>>>(x, gate_w);
    route_build_kernel<<<1, 256>>>();
    convert_kernel<<<(NT*HID/4)/256, 256>>>(x, 0);
    convert_kernel<<<(NE*HID*FF/4)/256, 256>>>(w_gate, 1);
    convert_kernel<<<(NE*HID*FF/4)/256, 256>>>(w_up,   2);
    convert_kernel<<<(NE*FF*HID/4)/256, 256>>>(w_down, 3);
    dim3 g1(MAX_TILES, FF/BN);     // 40 x 64
    gemm1_kernel<<<g1, 256>>>();
    dim3 g2(MAX_TILES, HID/BN2);   // 40 x 8
    gemm2_kernel<<<g2, 256>>>();
    combine_kernel<<<NT, 256>>>(out);
}

// round 12
// speedup vs baseline: 1.5192x; 1.2009x over previous
#include <cuda_runtime.h>
#include <cuda_fp16.h>
#include <math.h>
#include <stdint.h>

#define HID   1024
#define FF    4096
#define NE    8
#define NT    2048
#define NSLOT (NT*2)
#define BM    128
#define BN    64
#define KC    64
#define MAX_TILES 40

// ---------------- scratch (static device globals; no allocation) ------------
__device__ __align__(256) int   g_top_i[NT*2];
__device__ __align__(256) float g_top_w[NT*2];
__device__ __align__(256) int   g_slot_token[NSLOT];
__device__ __align__(256) int   g_token_slot[NT*2];
__device__ __align__(256) int   g_tile_e[MAX_TILES];
__device__ __align__(256) int   g_tile_row0[MAX_TILES];
__device__ __align__(256) int   g_tile_nrows[MAX_TILES];
__device__ int   g_num_tiles;

// fp16 planes: activations split hi/lo, weights single fp16
__device__ __align__(256) __half g_xh[NT*HID];
__device__ __align__(256) __half g_xl[NT*HID];
__device__ __align__(256) __half g_wg16[(size_t)NE*HID*FF];
__device__ __align__(256) __half g_wu16[(size_t)NE*HID*FF];
__device__ __align__(256) __half g_wd16[(size_t)NE*FF*HID];
__device__ __align__(256) __half g_hh[(size_t)NSLOT*FF];
__device__ __align__(256) __half g_hl[(size_t)NSLOT*FF];
__device__ __align__(256) float g_dout[(size_t)NSLOT*HID];

// ---------------- helpers ---------------------------------------------------
__device__ __forceinline__ uint32_t smem_u32(const void* p) {
    uint32_t a;
    asm("{ .reg .u64 t; cvta.to.shared.u64 t, %1; cvt.u32.u64 %0, t; }" : "=r"(a) : "l"(p));
    return a;
}
__device__ __forceinline__ void cp16(uint32_t dst, const void* src) {
    asm volatile("cp.async.cg.shared.global [%0], [%1], 16;"
        :: "r"(dst), "l"(__cvta_generic_to_global(src)) : "memory");
}
#define CP_COMMIT() asm volatile("cp.async.commit_group;" ::: "memory")
#define CP_WAIT0()  asm volatile("cp.async.wait_group 0;" ::: "memory")

__device__ __forceinline__ void ldsm4(uint32_t* r, uint32_t addr) {
    asm volatile("ldmatrix.sync.aligned.m8n8.x4.shared.b16 {%0,%1,%2,%3}, [%4];"
        : "=r"(r[0]), "=r"(r[1]), "=r"(r[2]), "=r"(r[3]) : "r"(addr));
}
__device__ __forceinline__ void ldsm4t(uint32_t* r, uint32_t addr) {
    asm volatile("ldmatrix.sync.aligned.m8n8.x4.trans.shared.b16 {%0,%1,%2,%3}, [%4];"
        : "=r"(r[0]), "=r"(r[1]), "=r"(r[2]), "=r"(r[3]) : "r"(addr));
}
__device__ __forceinline__ void mma16816(float* d, const uint32_t* a, const uint32_t* b) {
    asm volatile("mma.sync.aligned.m16n8k16.row.col.f32.f16.f16.f32 "
        "{%0,%1,%2,%3}, {%4,%5,%6,%7}, {%8,%9}, {%0,%1,%2,%3};"
        : "+f"(d[0]), "+f"(d[1]), "+f"(d[2]), "+f"(d[3])
        : "r"(a[0]), "r"(a[1]), "r"(a[2]), "r"(a[3]), "r"(b[0]), "r"(b[1]));
}
__device__ __forceinline__ uint32_t pack_h2(float a, float b) {
    unsigned short lo = __half_as_ushort(__float2half_rn(a));
    unsigned short hi = __half_as_ushort(__float2half_rn(b));
    return (uint32_t)lo | ((uint32_t)hi << 16);
}

// SMEM tile strides (bytes): conflict-free for ldmatrix (row step == 4 mod 32 banks)
#define A_STRIDE 144    // 128B data (64 fp16) + 16B pad
#define B_STRIDE 144    // 128B data (64 fp16) + 16B pad
#define B2_STRIDE 272   // 256B data (128 fp16) + 16B pad

#define A_PLANE   (BM*A_STRIDE)          // 18432
#define B1_PLANE  (KC*B_STRIDE)          // 9216
#define G1_SMEM   (2*A_PLANE + 2*B1_PLANE)   // 55296
#define G2_SMEM   (2*A_PLANE + KC*B2_STRIDE) // 54272

// ---------------- converts (dst selected ON DEVICE) -------------------------
__global__ void convert_kernel(const float* __restrict__ src, int which)
{
    size_t i = (size_t)blockIdx.x * blockDim.x + threadIdx.x;   // float4 index
    float4 v = *(const float4*)(src + i * 4);
    if (which == 0) {
        float h0 = __half2float(__float2half_rn(v.x));
        float h1 = __half2float(__float2half_rn(v.y));
        float h2 = __half2float(__float2half_rn(v.z));
        float h3 = __half2float(__float2half_rn(v.w));
        *(uint2*)(g_xh + i*4) = make_uint2(pack_h2(v.x, v.y), pack_h2(v.z, v.w));
        *(uint2*)(g_xl + i*4) = make_uint2(pack_h2(v.x - h0, v.y - h1), pack_h2(v.z - h2, v.w - h3));
    } else {
        __half* d = (which == 1) ? g_wg16 : (which == 2) ? g_wu16 : g_wd16;
        *(uint2*)(d + i*4) = make_uint2(pack_h2(v.x, v.y), pack_h2(v.z, v.w));
    }
}

// ---------------- router ----------------------------------------------------
__global__ void router_kernel(const float* __restrict__ x, const float* __restrict__ gw)
{
    int wid  = (blockIdx.x * blockDim.x + threadIdx.x) >> 5;
    int lane = threadIdx.x & 31;
    if (wid >= NT) return;
    const float* xr = x + (size_t)wid * HID;
    float acc[NE];
    #pragma unroll
    for (int e = 0; e < NE; e++) acc[e] = 0.f;
    for (int h = lane; h < HID; h += 32) {
        float  xv = xr[h];
        float4 a  = *(const float4*)(gw + h*NE);
        float4 b  = *(const float4*)(gw + h*NE + 4);
        acc[0] += xv*a.x; acc[1] += xv*a.y; acc[2] += xv*a.z; acc[3] += xv*a.w;
        acc[4] += xv*b.x; acc[5] += xv*b.y; acc[6] += xv*b.z; acc[7] += xv*b.w;
    }
    #pragma unroll
    for (int e = 0; e < NE; e++)
        #pragma unroll
        for (int o = 16; o > 0; o >>= 1)
            acc[e] += __shfl_xor_sync(0xffffffffu, acc[e], o);
    if (lane == 0) {
        float m = acc[0];
        #pragma unroll
        for (int e = 1; e < NE; e++) m = fmaxf(m, acc[e]);
        float p[NE], s = 0.f;
        #pragma unroll
        for (int e = 0; e < NE; e++) { p[e] = expf(acc[e] - m); s += p[e]; }
        float inv = 1.f / s;
        #pragma unroll
        for (int e = 0; e < NE; e++) p[e] *= inv;
        int i0 = 0;
        #pragma unroll
        for (int e = 1; e < NE; e++) if (p[e] > p[i0]) i0 = e;
        int i1 = (i0 == 0) ? 1 : 0;
        #pragma unroll
        for (int e = 0; e < NE; e++) if (e != i0 && p[e] > p[i1]) i1 = e;
        float w0 = 1.f / (1.f + expf(p[i1] - p[i0]));
        g_top_i[wid*2]   = i0;  g_top_i[wid*2+1] = i1;
        g_top_w[wid*2]   = w0;  g_top_w[wid*2+1] = 1.f - w0;
    }
}

// ---------------- routing build (deterministic) ------------------------------
__global__ void route_build_kernel()
{
    __shared__ int counts[NE];
    __shared__ int offsets[NE+1];
    const int tid  = threadIdx.x;
    const int warp = tid >> 5;
    const int lane = tid & 31;
    int c = 0;
    for (int p = lane; p < NSLOT; p += 32)
        if (g_top_i[p] == warp) c++;
    #pragma unroll
    for (int o = 16; o > 0; o >>= 1) c += __shfl_down_sync(0xffffffffu, c, o);
    if (lane == 0) counts[warp] = c;
    __syncthreads();
    if (tid == 0) {
        int s = 0;
        for (int e = 0; e < NE; e++) { offsets[e] = s; s += counts[e]; }
        offsets[NE] = s;
    }
    __syncthreads();
    int base = offsets[warp];
    for (int p0 = 0; p0 < NSLOT; p0 += 32) {
        int p = p0 + lane;
        bool f = (g_top_i[p] == warp);
        unsigned msk = __ballot_sync(0xffffffffu, f);
        if (f) {
            int slot = base + __popc(msk & ((1u << lane) - 1u));
            g_slot_token[slot] = p >> 1;
            g_token_slot[p]    = slot;
        }
        base += __popc(msk);
    }
    __syncthreads();
    if (tid == 0) {
        int nt = 0;
        for (int e = 0; e < NE; e++) {
            int cnt = counts[e];
            for (int r = 0; r < cnt; r += BM) {
                g_tile_e[nt] = e;
                g_tile_row0[nt] = offsets[e] + r;
                g_tile_nrows[nt] = min(BM, cnt - r);
                nt++;
            }
        }
        g_num_tiles = nt;
    }
}

// ---------------- GEMM1: fp16x2 (A split, B single), KC=64, SwiGLU ----------
__global__ void __launch_bounds__(256) gemm1_kernel()
{
    const int tile = blockIdx.x;
    if (tile >= g_num_tiles) return;
    const int e     = g_tile_e[tile];
    const int row0  = g_tile_row0[tile];
    const int nrows = g_tile_nrows[tile];
    const int n0    = blockIdx.y * BN;

    extern __shared__ __align__(16) char sm[];
    __shared__ int stok[BM];

    const int tid = threadIdx.x, lane = tid & 31, wid = tid >> 5;
    const int warpM = wid & 3, warpN = wid >> 2;

    if (tid < BM) stok[tid] = (tid < nrows) ? g_slot_token[row0 + tid] : 0;
    __syncthreads();

    const __half* asrc[2] = { g_xh, g_xl };
    const __half* bsrc[2] = {
        g_wg16 + (size_t)e*HID*FF, g_wu16 + (size_t)e*HID*FF };

    const uint32_t sa = smem_u32(sm);
    const uint32_t sbb = sa + 2*A_PLANE;

    float ag[2][4][4], au[2][4][4];
    #pragma unroll
    for (int i = 0; i < 2; i++)
        #pragma unroll
        for (int g = 0; g < 4; g++)
            #pragma unroll
            for (int r = 0; r < 4; r++) { ag[i][g][r] = 0.f; au[i][g][r] = 0.f; }

    for (int ch = 0; ch < HID/KC; ch++) {      // 16 chunks
        const int k0 = ch * KC;
        // A: 2 planes x 128 rows x 8 segs = 2048 cp16
        #pragma unroll
        for (int t = 0; t < 8; t++) {
            int idx = tid + t*256;
            int p = idx >> 10, row = (idx >> 3) & 127, seg = idx & 7;
            cp16(sa + p*A_PLANE + row*A_STRIDE + seg*16,
                 asrc[p] + (size_t)stok[row]*HID + k0 + seg*8);
        }
        // B: 2 mats x 64 k-rows x 8 segs = 1024 cp16
        #pragma unroll
        for (int t = 0; t < 4; t++) {
            int idx = tid + t*256;
            int p = idx >> 9, row = (idx >> 3) & 63, seg = idx & 7;
            cp16(sbb + p*B1_PLANE + row*B_STRIDE + seg*16,
                 bsrc[p] + (size_t)(k0+row)*FF + n0 + seg*8);
        }
        CP_COMMIT(); CP_WAIT0();
        __syncthreads();

        #pragma unroll
        for (int kk = 0; kk < 4; kk++) {
            uint32_t af[2][2][4];     // [plane][i]
            #pragma unroll
            for (int i = 0; i < 2; i++) {
                uint32_t ar = (uint32_t)(warpM*32 + i*16 + (lane & 15))*A_STRIDE
                              + kk*32 + (lane >> 4)*16;
                ldsm4(af[0][i], sa + ar);
                ldsm4(af[1][i], sa + A_PLANE + ar);
            }
            uint32_t br = (uint32_t)(kk*16 + (lane & 15))*B_STRIDE
                          + warpN*64 + (lane >> 4)*16;
            uint32_t bf[2][4][2];     // [mat: gate/up][ngroup]
            #pragma unroll
            for (int p = 0; p < 2; p++) {
                uint32_t q0[4], q1[4];
                ldsm4t(q0, sbb + p*B1_PLANE + br);
                ldsm4t(q1, sbb + p*B1_PLANE + br + 32);
                bf[p][0][0]=q0[0]; bf[p][0][1]=q0[1];
                bf[p][1][0]=q0[2]; bf[p][1][1]=q0[3];
                bf[p][2][0]=q1[0]; bf[p][2][1]=q1[1];
                bf[p][3][0]=q1[2]; bf[p][3][1]=q1[3];
            }
            #pragma unroll
            for (int i = 0; i < 2; i++)
                #pragma unroll
                for (int g = 0; g < 4; g++) {
                    mma16816(ag[i][g], af[0][i], bf[0][g]);
                    mma16816(ag[i][g], af[1][i], bf[0][g]);
                    mma16816(au[i][g], af[0][i], bf[1][g]);
                    mma16816(au[i][g], af[1][i], bf[1][g]);
                }
        }
        __syncthreads();
    }

    const int qr = lane >> 2;
    const int qc = 2 * (lane & 3);
    #pragma unroll
    for (int i = 0; i < 2; i++)
        #pragma unroll
        for (int g = 0; g < 4; g++) {
            int col = n0 + warpN*32 + g*8 + qc;
            #pragma unroll
            for (int half = 0; half < 2; half++) {
                int tm = warpM*32 + i*16 + qr + half*8;
                if (tm < nrows) {
                    float g0 = ag[i][g][half*2],   u0 = au[i][g][half*2];
                    float g1 = ag[i][g][half*2+1], u1 = au[i][g][half*2+1];
                    float v0 = (g0 / (1.f + __expf(-g0))) * u0;
                    float v1 = (g1 / (1.f + __expf(-g1))) * u1;
                    float hh0 = __half2float(__float2half_rn(v0));
                    float hh1 = __half2float(__float2half_rn(v1));
                    size_t off = (size_t)(row0 + tm) * FF + col;
                    *(uint32_t*)(g_hh + off) = pack_h2(v0, v1);
                    *(uint32_t*)(g_hl + off) = pack_h2(v0 - hh0, v1 - hh1);
                }
            }
        }
}

// ---------------- GEMM2: fp16x2 down-proj, BN=128, KC=64 --------------------
#define BN2 128
__global__ void __launch_bounds__(256) gemm2_kernel()
{
    const int tile = blockIdx.x;
    if (tile >= g_num_tiles) return;
    const int e     = g_tile_e[tile];
    const int row0  = g_tile_row0[tile];
    const int nrows = g_tile_nrows[tile];
    const int n0    = blockIdx.y * BN2;

    extern __shared__ __align__(16) char sm[];

    const int tid = threadIdx.x, lane = tid & 31, wid = tid >> 5;
    const int warpM = wid & 3, warpN = wid >> 2;           // warpN covers 64 cols

    const __half* asrc[2] = { g_hh, g_hl };
    const __half* bsrc = g_wd16 + (size_t)e*FF*HID;

    const uint32_t sa = smem_u32(sm);
    const uint32_t sbb = sa + 2*A_PLANE;

    float acc[2][8][4];
    #pragma unroll
    for (int i = 0; i < 2; i++)
        #pragma unroll
        for (int g = 0; g < 8; g++)
            #pragma unroll
            for (int r = 0; r < 4; r++) acc[i][g][r] = 0.f;

    for (int ch = 0; ch < FF/KC; ch++) {       // 64 chunks
        const int k0 = ch * KC;
        // A: 2 planes x 128 rows x 8 segs = 2048 cp16
        #pragma unroll
        for (int t = 0; t < 8; t++) {
            int idx = tid + t*256;
            int p = idx >> 10, row = (idx >> 3) & 127, seg = idx & 7;
            int r = row0 + row; if (r > NSLOT-1) r = NSLOT-1;
            cp16(sa + p*A_PLANE + row*A_STRIDE + seg*16,
                 asrc[p] + (size_t)r*FF + k0 + seg*8);
        }
        // B: 64 k-rows x 16 segs = 1024 cp16
        #pragma unroll
        for (int t = 0; t < 4; t++) {
            int idx = tid + t*256;
            int row = idx >> 4, seg = idx & 15;
            cp16(sbb + row*B2_STRIDE + seg*16,
                 bsrc + (size_t)(k0+row)*HID + n0 + seg*8);
        }
        CP_COMMIT(); CP_WAIT0();
        __syncthreads();

        #pragma unroll
        for (int kk = 0; kk < 4; kk++) {
            uint32_t af[2][2][4];
            #pragma unroll
            for (int i = 0; i < 2; i++) {
                uint32_t ar = (uint32_t)(warpM*32 + i*16 + (lane & 15))*A_STRIDE
                              + kk*32 + (lane >> 4)*16;
                ldsm4(af[0][i], sa + ar);
                ldsm4(af[1][i], sa + A_PLANE + ar);
            }
            uint32_t br = (uint32_t)(kk*16 + (lane & 15))*B2_STRIDE
                          + warpN*128 + (lane >> 4)*16;
            uint32_t bf[8][2];
            #pragma unroll
            for (int q = 0; q < 4; q++) {
                uint32_t qq[4];
                ldsm4t(qq, sbb + br + q*32);
                bf[2*q  ][0]=qq[0]; bf[2*q  ][1]=qq[1];
                bf[2*q+1][0]=qq[2]; bf[2*q+1][1]=qq[3];
            }
            #pragma unroll
            for (int i = 0; i < 2; i++)
                #pragma unroll
                for (int g = 0; g < 8; g++) {
                    mma16816(acc[i][g], af[0][i], bf[g]);
                    mma16816(acc[i][g], af[1][i], bf[g]);
                }
        }
        __syncthreads();
    }

    const int qr = lane >> 2;
    const int qc = 2 * (lane & 3);
    #pragma unroll
    for (int i = 0; i < 2; i++)
        #pragma unroll
        for (int g = 0; g < 8; g++) {
            int col = n0 + warpN*64 + g*8 + qc;   // byte offset 128 == 64 columns
            #pragma unroll
            for (int half = 0; half < 2; half++) {
                int tm = warpM*32 + i*16 + qr + half*8;
                if (tm < nrows) {
                    float2 v = make_float2(acc[i][g][half*2], acc[i][g][half*2+1]);
                    *(float2*)(g_dout + (size_t)(row0 + tm)*HID + col) = v;
                }
            }
        }
}

// ---------------- combine ----------------------------------------------------
__global__ void combine_kernel(float* __restrict__ out)
{
    const int t  = blockIdx.x;
    const int s0 = g_token_slot[t*2];
    const int s1 = g_token_slot[t*2+1];
    const float w0 = g_top_w[t*2];
    const float w1 = g_top_w[t*2+1];
    const int h = threadIdx.x << 2;
    float4 d0 = *(const float4*)(g_dout + (size_t)s0*HID + h);
    float4 d1 = *(const float4*)(g_dout + (size_t)s1*HID + h);
    float4 o;
    o.x = w0*d0.x + w1*d1.x;
    o.y = w0*d0.y + w1*d1.y;
    o.z = w0*d0.z + w1*d1.z;
    o.w = w0*d0.w + w1*d1.w;
    *(float4*)(out + (size_t)t*HID + h) = o;
}

// ---------------------------------------------------------------------------
extern "C" void kernel_launch(void* const* d_in, const int* in_sizes, int n_in,
                              void* d_out, int out_size)
{
    const float* x      = (const float*)d_in[0];
    const float* gate_w = (const float*)d_in[1];
    const float* w_gate = (const float*)d_in[2];
    const float* w_up   = (const float*)d_in[3];
    const float* w_down = (const float*)d_in[4];
    float* out = (float*)d_out;

    static int attr_done = 0;
    if (!attr_done) {
        cudaFuncSetAttribute(gemm1_kernel, cudaFuncAttributeMaxDynamicSharedMemorySize, G1_SMEM);
        cudaFuncSetAttribute(gemm2_kernel, cudaFuncAttributeMaxDynamicSharedMemorySize, G2_SMEM);
        attr_done = 1;
    }

    router_kernel<<<NT*32/256, 256>>>(x, gate_w);
    route_build_kernel<<<1, 256>>>();
    convert_kernel<<<(NT*HID/4)/256, 256>>>(x, 0);
    convert_kernel<<<(NE*HID*FF/4)/256, 256>>>(w_gate, 1);
    convert_kernel<<<(NE*HID*FF/4)/256, 256>>>(w_up,   2);
    convert_kernel<<<(NE*FF*HID/4)/256, 256>>>(w_down, 3);
    dim3 g1(MAX_TILES, FF/BN);     // 40 x 64
    gemm1_kernel<<<g1, 256, G1_SMEM>>>();
    dim3 g2(MAX_TILES, HID/BN2);   // 40 x 8
    gemm2_kernel<<<g2, 256, G2_SMEM>>>();
    combine_kernel<<<NT, 256>>>(out);
}

// round 13
// speedup vs baseline: 1.5270x; 1.0051x over previous
#include <cuda_runtime.h>
#include <cuda_fp16.h>
#include <math.h>
#include <stdint.h>

#define HID   1024
#define FF    4096
#define NE    8
#define NT    2048
#define NSLOT (NT*2)
#define BM    128
#define BN    64
#define MAX_TILES 40

// ---------------- scratch (static device globals; no allocation) ------------
__device__ __align__(256) int   g_top_i[NT*2];
__device__ __align__(256) float g_top_w[NT*2];
__device__ __align__(256) int   g_slot_token[NSLOT];
__device__ __align__(256) int   g_token_slot[NT*2];
__device__ __align__(256) int   g_tile_e[MAX_TILES];
__device__ __align__(256) int   g_tile_row0[MAX_TILES];
__device__ __align__(256) int   g_tile_nrows[MAX_TILES];
__device__ int   g_num_tiles;

// fp16 planes: activations split hi/lo, weights single fp16
__device__ __align__(256) __half g_xh[NT*HID];
__device__ __align__(256) __half g_xl[NT*HID];
__device__ __align__(256) __half g_wg16[(size_t)NE*HID*FF];
__device__ __align__(256) __half g_wu16[(size_t)NE*HID*FF];
__device__ __align__(256) __half g_wd16[(size_t)NE*FF*HID];
__device__ __align__(256) __half g_hh[(size_t)NSLOT*FF];
__device__ __align__(256) __half g_hl[(size_t)NSLOT*FF];
__device__ __align__(256) float g_dout[(size_t)NSLOT*HID];

// ---------------- helpers ---------------------------------------------------
__device__ __forceinline__ uint32_t smem_u32(const void* p) {
    uint32_t a;
    asm("{ .reg .u64 t; cvta.to.shared.u64 t, %1; cvt.u32.u64 %0, t; }" : "=r"(a) : "l"(p));
    return a;
}
__device__ __forceinline__ void cp16(uint32_t dst, const void* src) {
    asm volatile("cp.async.cg.shared.global [%0], [%1], 16;"
        :: "r"(dst), "l"(__cvta_generic_to_global(src)) : "memory");
}
#define CP_COMMIT() asm volatile("cp.async.commit_group;" ::: "memory")
#define CP_WAIT0()  asm volatile("cp.async.wait_group 0;" ::: "memory")

__device__ __forceinline__ void ldsm4(uint32_t* r, uint32_t addr) {
    asm volatile("ldmatrix.sync.aligned.m8n8.x4.shared.b16 {%0,%1,%2,%3}, [%4];"
        : "=r"(r[0]), "=r"(r[1]), "=r"(r[2]), "=r"(r[3]) : "r"(addr));
}
__device__ __forceinline__ void ldsm4t(uint32_t* r, uint32_t addr) {
    asm volatile("ldmatrix.sync.aligned.m8n8.x4.trans.shared.b16 {%0,%1,%2,%3}, [%4];"
        : "=r"(r[0]), "=r"(r[1]), "=r"(r[2]), "=r"(r[3]) : "r"(addr));
}
__device__ __forceinline__ void mma16816(float* d, const uint32_t* a, const uint32_t* b) {
    asm volatile("mma.sync.aligned.m16n8k16.row.col.f32.f16.f16.f32 "
        "{%0,%1,%2,%3}, {%4,%5,%6,%7}, {%8,%9}, {%0,%1,%2,%3};"
        : "+f"(d[0]), "+f"(d[1]), "+f"(d[2]), "+f"(d[3])
        : "r"(a[0]), "r"(a[1]), "r"(a[2]), "r"(a[3]), "r"(b[0]), "r"(b[1]));
}
__device__ __forceinline__ uint32_t pack_h2(float a, float b) {
    unsigned short lo = __half_as_ushort(__float2half_rn(a));
    unsigned short hi = __half_as_ushort(__float2half_rn(b));
    return (uint32_t)lo | ((uint32_t)hi << 16);
}

// SMEM strides (bytes): all row steps == 4 mod 32 banks -> ldmatrix conflict-free
#define A1_STRIDE 272   // GEMM1 A: 256B data (128 fp16 = KC1) + 16B pad
#define B1_STRIDE 144   // GEMM1 B: 128B data (64 fp16 = BN) + 16B pad
#define A2_STRIDE 144   // GEMM2 A: 128B data (64 fp16 = KC2) + 16B pad
#define B2_STRIDE 272   // GEMM2 B: 256B data (128 fp16 = BN2) + 16B pad

#define KC1 128
#define KC2 64
#define A1_PLANE (BM*A1_STRIDE)           // 34816
#define B1_PLANE (KC1*B1_STRIDE)          // 18432
#define A2_PLANE (BM*A2_STRIDE)           // 18432
#define G1_SMEM  (2*A1_PLANE + 2*B1_PLANE)    // 106496
#define G2_SMEM  (2*A2_PLANE + KC2*B2_STRIDE) // 54272

// ---------------- converts --------------------------------------------------
__global__ void convert_x_kernel(const float* __restrict__ src)
{
    size_t i = (size_t)blockIdx.x * blockDim.x + threadIdx.x;   // float4 index
    float4 v = *(const float4*)(src + i * 4);
    float h0 = __half2float(__float2half_rn(v.x));
    float h1 = __half2float(__float2half_rn(v.y));
    float h2 = __half2float(__float2half_rn(v.z));
    float h3 = __half2float(__float2half_rn(v.w));
    *(uint2*)(g_xh + i*4) = make_uint2(pack_h2(v.x, v.y), pack_h2(v.z, v.w));
    *(uint2*)(g_xl + i*4) = make_uint2(pack_h2(v.x - h0, v.y - h1), pack_h2(v.z - h2, v.w - h3));
}

// one launch converts all three weight tensors (blockIdx.y selects)
__global__ void convert_w_kernel(const float* __restrict__ wg,
                                 const float* __restrict__ wu,
                                 const float* __restrict__ wd)
{
    const float* src = (blockIdx.y == 0) ? wg : (blockIdx.y == 1) ? wu : wd;
    __half* dst = (blockIdx.y == 0) ? g_wg16 : (blockIdx.y == 1) ? g_wu16 : g_wd16;
    size_t i = (size_t)blockIdx.x * blockDim.x + threadIdx.x;
    float4 v = *(const float4*)(src + i * 4);
    *(uint2*)(dst + i*4) = make_uint2(pack_h2(v.x, v.y), pack_h2(v.z, v.w));
}

// ---------------- router ----------------------------------------------------
__global__ void router_kernel(const float* __restrict__ x, const float* __restrict__ gw)
{
    int wid  = (blockIdx.x * blockDim.x + threadIdx.x) >> 5;
    int lane = threadIdx.x & 31;
    if (wid >= NT) return;
    const float* xr = x + (size_t)wid * HID;
    float acc[NE];
    #pragma unroll
    for (int e = 0; e < NE; e++) acc[e] = 0.f;
    for (int h = lane; h < HID; h += 32) {
        float  xv = xr[h];
        float4 a  = *(const float4*)(gw + h*NE);
        float4 b  = *(const float4*)(gw + h*NE + 4);
        acc[0] += xv*a.x; acc[1] += xv*a.y; acc[2] += xv*a.z; acc[3] += xv*a.w;
        acc[4] += xv*b.x; acc[5] += xv*b.y; acc[6] += xv*b.z; acc[7] += xv*b.w;
    }
    #pragma unroll
    for (int e = 0; e < NE; e++)
        #pragma unroll
        for (int o = 16; o > 0; o >>= 1)
            acc[e] += __shfl_xor_sync(0xffffffffu, acc[e], o);
    if (lane == 0) {
        float m = acc[0];
        #pragma unroll
        for (int e = 1; e < NE; e++) m = fmaxf(m, acc[e]);
        float p[NE], s = 0.f;
        #pragma unroll
        for (int e = 0; e < NE; e++) { p[e] = expf(acc[e] - m); s += p[e]; }
        float inv = 1.f / s;
        #pragma unroll
        for (int e = 0; e < NE; e++) p[e] *= inv;
        int i0 = 0;
        #pragma unroll
        for (int e = 1; e < NE; e++) if (p[e] > p[i0]) i0 = e;
        int i1 = (i0 == 0) ? 1 : 0;
        #pragma unroll
        for (int e = 0; e < NE; e++) if (e != i0 && p[e] > p[i1]) i1 = e;
        float w0 = 1.f / (1.f + expf(p[i1] - p[i0]));
        g_top_i[wid*2]   = i0;  g_top_i[wid*2+1] = i1;
        g_top_w[wid*2]   = w0;  g_top_w[wid*2+1] = 1.f - w0;
    }
}

// ---------------- routing build (deterministic) ------------------------------
__global__ void route_build_kernel()
{
    __shared__ int counts[NE];
    __shared__ int offsets[NE+1];
    const int tid  = threadIdx.x;
    const int warp = tid >> 5;
    const int lane = tid & 31;
    int c = 0;
    for (int p = lane; p < NSLOT; p += 32)
        if (g_top_i[p] == warp) c++;
    #pragma unroll
    for (int o = 16; o > 0; o >>= 1) c += __shfl_down_sync(0xffffffffu, c, o);
    if (lane == 0) counts[warp] = c;
    __syncthreads();
    if (tid == 0) {
        int s = 0;
        for (int e = 0; e < NE; e++) { offsets[e] = s; s += counts[e]; }
        offsets[NE] = s;
    }
    __syncthreads();
    int base = offsets[warp];
    for (int p0 = 0; p0 < NSLOT; p0 += 32) {
        int p = p0 + lane;
        bool f = (g_top_i[p] == warp);
        unsigned msk = __ballot_sync(0xffffffffu, f);
        if (f) {
            int slot = base + __popc(msk & ((1u << lane) - 1u));
            g_slot_token[slot] = p >> 1;
            g_token_slot[p]    = slot;
        }
        base += __popc(msk);
    }
    __syncthreads();
    if (tid == 0) {
        int nt = 0;
        for (int e = 0; e < NE; e++) {
            int cnt = counts[e];
            for (int r = 0; r < cnt; r += BM) {
                g_tile_e[nt] = e;
                g_tile_row0[nt] = offsets[e] + r;
                g_tile_nrows[nt] = min(BM, cnt - r);
                nt++;
            }
        }
        g_num_tiles = nt;
    }
}

// ---------------- GEMM1: fp16x2 (A split, B single), KC=128, SwiGLU ---------
__global__ void __launch_bounds__(256) gemm1_kernel()
{
    const int tile = blockIdx.x;
    if (tile >= g_num_tiles) return;
    const int e     = g_tile_e[tile];
    const int row0  = g_tile_row0[tile];
    const int nrows = g_tile_nrows[tile];
    const int n0    = blockIdx.y * BN;

    extern __shared__ __align__(16) char sm[];
    __shared__ int stok[BM];

    const int tid = threadIdx.x, lane = tid & 31, wid = tid >> 5;
    const int warpM = wid & 3, warpN = wid >> 2;

    if (tid < BM) stok[tid] = (tid < nrows) ? g_slot_token[row0 + tid] : 0;
    __syncthreads();

    const __half* asrc[2] = { g_xh, g_xl };
    const __half* bsrc[2] = {
        g_wg16 + (size_t)e*HID*FF, g_wu16 + (size_t)e*HID*FF };

    const uint32_t sa = smem_u32(sm);
    const uint32_t sbb = sa + 2*A1_PLANE;

    float ag[2][4][4], au[2][4][4];
    #pragma unroll
    for (int i = 0; i < 2; i++)
        #pragma unroll
        for (int g = 0; g < 4; g++)
            #pragma unroll
            for (int r = 0; r < 4; r++) { ag[i][g][r] = 0.f; au[i][g][r] = 0.f; }

    for (int ch = 0; ch < HID/KC1; ch++) {     // 8 chunks
        const int k0 = ch * KC1;
        // A: 2 planes x 128 rows x 16 segs = 4096 cp16
        #pragma unroll
        for (int t = 0; t < 16; t++) {
            int idx = tid + t*256;
            int p = idx >> 11, row = (idx >> 4) & 127, seg = idx & 15;
            cp16(sa + p*A1_PLANE + row*A1_STRIDE + seg*16,
                 asrc[p] + (size_t)stok[row]*HID + k0 + seg*8);
        }
        // B: 2 mats x 128 k-rows x 8 segs = 2048 cp16
        #pragma unroll
        for (int t = 0; t < 8; t++) {
            int idx = tid + t*256;
            int p = idx >> 10, row = (idx >> 3) & 127, seg = idx & 7;
            cp16(sbb + p*B1_PLANE + row*B1_STRIDE + seg*16,
                 bsrc[p] + (size_t)(k0+row)*FF + n0 + seg*8);
        }
        CP_COMMIT(); CP_WAIT0();
        __syncthreads();

        #pragma unroll
        for (int kk = 0; kk < 8; kk++) {
            uint32_t af[2][2][4];     // [plane][i]
            #pragma unroll
            for (int i = 0; i < 2; i++) {
                uint32_t ar = (uint32_t)(warpM*32 + i*16 + (lane & 15))*A1_STRIDE
                              + kk*32 + (lane >> 4)*16;
                ldsm4(af[0][i], sa + ar);
                ldsm4(af[1][i], sa + A1_PLANE + ar);
            }
            uint32_t br = (uint32_t)(kk*16 + (lane & 15))*B1_STRIDE
                          + warpN*64 + (lane >> 4)*16;
            uint32_t bf[2][4][2];     // [mat: gate/up][ngroup]
            #pragma unroll
            for (int p = 0; p < 2; p++) {
                uint32_t q0[4], q1[4];
                ldsm4t(q0, sbb + p*B1_PLANE + br);
                ldsm4t(q1, sbb + p*B1_PLANE + br + 32);
                bf[p][0][0]=q0[0]; bf[p][0][1]=q0[1];
                bf[p][1][0]=q0[2]; bf[p][1][1]=q0[3];
                bf[p][2][0]=q1[0]; bf[p][2][1]=q1[1];
                bf[p][3][0]=q1[2]; bf[p][3][1]=q1[3];
            }
            #pragma unroll
            for (int i = 0; i < 2; i++)
                #pragma unroll
                for (int g = 0; g < 4; g++) {
                    mma16816(ag[i][g], af[0][i], bf[0][g]);
                    mma16816(ag[i][g], af[1][i], bf[0][g]);
                    mma16816(au[i][g], af[0][i], bf[1][g]);
                    mma16816(au[i][g], af[1][i], bf[1][g]);
                }
        }
        __syncthreads();
    }

    const int qr = lane >> 2;
    const int qc = 2 * (lane & 3);
    #pragma unroll
    for (int i = 0; i < 2; i++)
        #pragma unroll
        for (int g = 0; g < 4; g++) {
            int col = n0 + warpN*32 + g*8 + qc;
            #pragma unroll
            for (int half = 0; half < 2; half++) {
                int tm = warpM*32 + i*16 + qr + half*8;
                if (tm < nrows) {
                    float g0 = ag[i][g][half*2],   u0 = au[i][g][half*2];
                    float g1 = ag[i][g][half*2+1], u1 = au[i][g][half*2+1];
                    float v0 = (g0 / (1.f + __expf(-g0))) * u0;
                    float v1 = (g1 / (1.f + __expf(-g1))) * u1;
                    float hh0 = __half2float(__float2half_rn(v0));
                    float hh1 = __half2float(__float2half_rn(v1));
                    size_t off = (size_t)(row0 + tm) * FF + col;
                    *(uint32_t*)(g_hh + off) = pack_h2(v0, v1);
                    *(uint32_t*)(g_hl + off) = pack_h2(v0 - hh0, v1 - hh1);
                }
            }
        }
}

// ---------------- GEMM2: fp16x2 down-proj, BN=128, KC=64 --------------------
#define BN2 128
__global__ void __launch_bounds__(256) gemm2_kernel()
{
    const int tile = blockIdx.x;
    if (tile >= g_num_tiles) return;
    const int e     = g_tile_e[tile];
    const int row0  = g_tile_row0[tile];
    const int nrows = g_tile_nrows[tile];
    const int n0    = blockIdx.y * BN2;

    extern __shared__ __align__(16) char sm[];

    const int tid = threadIdx.x, lane = tid & 31, wid = tid >> 5;
    const int warpM = wid & 3, warpN = wid >> 2;           // warpN covers 64 cols

    const __half* asrc[2] = { g_hh, g_hl };
    const __half* bsrc = g_wd16 + (size_t)e*FF*HID;

    const uint32_t sa = smem_u32(sm);
    const uint32_t sbb = sa + 2*A2_PLANE;

    float acc[2][8][4];
    #pragma unroll
    for (int i = 0; i < 2; i++)
        #pragma unroll
        for (int g = 0; g < 8; g++)
            #pragma unroll
            for (int r = 0; r < 4; r++) acc[i][g][r] = 0.f;

    for (int ch = 0; ch < FF/KC2; ch++) {      // 64 chunks
        const int k0 = ch * KC2;
        // A: 2 planes x 128 rows x 8 segs = 2048 cp16
        #pragma unroll
        for (int t = 0; t < 8; t++) {
            int idx = tid + t*256;
            int p = idx >> 10, row = (idx >> 3) & 127, seg = idx & 7;
            int r = row0 + row; if (r > NSLOT-1) r = NSLOT-1;
            cp16(sa + p*A2_PLANE + row*A2_STRIDE + seg*16,
                 asrc[p] + (size_t)r*FF + k0 + seg*8);
        }
        // B: 64 k-rows x 16 segs = 1024 cp16
        #pragma unroll
        for (int t = 0; t < 4; t++) {
            int idx = tid + t*256;
            int row = idx >> 4, seg = idx & 15;
            cp16(sbb + row*B2_STRIDE + seg*16,
                 bsrc + (size_t)(k0+row)*HID + n0 + seg*8);
        }
        CP_COMMIT(); CP_WAIT0();
        __syncthreads();

        #pragma unroll
        for (int kk = 0; kk < 4; kk++) {
            uint32_t af[2][2][4];
            #pragma unroll
            for (int i = 0; i < 2; i++) {
                uint32_t ar = (uint32_t)(warpM*32 + i*16 + (lane & 15))*A2_STRIDE
                              + kk*32 + (lane >> 4)*16;
                ldsm4(af[0][i], sa + ar);
                ldsm4(af[1][i], sa + A2_PLANE + ar);
            }
            uint32_t br = (uint32_t)(kk*16 + (lane & 15))*B2_STRIDE
                          + warpN*128 + (lane >> 4)*16;
            uint32_t bf[8][2];
            #pragma unroll
            for (int q = 0; q < 4; q++) {
                uint32_t qq[4];
                ldsm4t(qq, sbb + br + q*32);
                bf[2*q  ][0]=qq[0]; bf[2*q  ][1]=qq[1];
                bf[2*q+1][0]=qq[2]; bf[2*q+1][1]=qq[3];
            }
            #pragma unroll
            for (int i = 0; i < 2; i++)
                #pragma unroll
                for (int g = 0; g < 8; g++) {
                    mma16816(acc[i][g], af[0][i], bf[g]);
                    mma16816(acc[i][g], af[1][i], bf[g]);
                }
        }
        __syncthreads();
    }

    const int qr = lane >> 2;
    const int qc = 2 * (lane & 3);
    #pragma unroll
    for (int i = 0; i < 2; i++)
        #pragma unroll
        for (int g = 0; g < 8; g++) {
            int col = n0 + warpN*64 + g*8 + qc;   // byte offset 128 == 64 columns
            #pragma unroll
            for (int half = 0; half < 2; half++) {
                int tm = warpM*32 + i*16 + qr + half*8;
                if (tm < nrows) {
                    float2 v = make_float2(acc[i][g][half*2], acc[i][g][half*2+1]);
                    *(float2*)(g_dout + (size_t)(row0 + tm)*HID + col) = v;
                }
            }
        }
}

// ---------------- combine ----------------------------------------------------
__global__ void combine_kernel(float* __restrict__ out)
{
    const int t  = blockIdx.x;
    const int s0 = g_token_slot[t*2];
    const int s1 = g_token_slot[t*2+1];
    const float w0 = g_top_w[t*2];
    const float w1 = g_top_w[t*2+1];
    const int h = threadIdx.x << 2;
    float4 d0 = *(const float4*)(g_dout + (size_t)s0*HID + h);
    float4 d1 = *(const float4*)(g_dout + (size_t)s1*HID + h);
    float4 o;
    o.x = w0*d0.x + w1*d1.x;
    o.y = w0*d0.y + w1*d1.y;
    o.z = w0*d0.z + w1*d1.z;
    o.w = w0*d0.w + w1*d1.w;
    *(float4*)(out + (size_t)t*HID + h) = o;
}

// ---------------------------------------------------------------------------
extern "C" void kernel_launch(void* const* d_in, const int* in_sizes, int n_in,
                              void* d_out, int out_size)
{
    const float* x      = (const float*)d_in[0];
    const float* gate_w = (const float*)d_in[1];
    const float* w_gate = (const float*)d_in[2];
    const float* w_up   = (const float*)d_in[3];
    const float* w_down = (const float*)d_in[4];
    float* out = (float*)d_out;

    static int attr_done = 0;
    if (!attr_done) {
        cudaFuncSetAttribute(gemm1_kernel, cudaFuncAttributeMaxDynamicSharedMemorySize, G1_SMEM);
        cudaFuncSetAttribute(gemm2_kernel, cudaFuncAttributeMaxDynamicSharedMemorySize, G2_SMEM);
        attr_done = 1;
    }

    router_kernel<<<NT*32/256, 256>>>(x, gate_w);
    route_build_kernel<<<1, 256>>>();
    convert_x_kernel<<<(NT*HID/4)/256, 256>>>(x);
    {
        dim3 gw((NE*HID*FF/4)/256, 3);
        convert_w_kernel<<<gw, 256>>>(w_gate, w_up, w_down);
    }
    dim3 g1(MAX_TILES, FF/BN);     // 40 x 64
    gemm1_kernel<<<g1, 256, G1_SMEM>>>();
    dim3 g2(MAX_TILES, HID/BN2);   // 40 x 8
    gemm2_kernel<<<g2, 256, G2_SMEM>>>();
    combine_kernel<<<NT, 256>>>(out);
}

// round 14
// speedup vs baseline: 2.5125x; 1.6454x over previous
#include <cuda_runtime.h>
#include <cuda_fp16.h>
#include <math.h>
#include <stdint.h>

#define HID   1024
#define FF    4096
#define NE    8
#define NT    2048
#define NSLOT (NT*2)
#define BM    128
#define BN    64
#define MAX_TILES 40

// ---------------- scratch (static device globals; no allocation) ------------
__device__ __align__(256) int   g_top_i[NT*2];
__device__ __align__(256) float g_top_w[NT*2];
__device__ __align__(256) int   g_slot_token[NSLOT];
__device__ __align__(256) int   g_token_slot[NT*2];
__device__ __align__(256) int   g_tile_e[MAX_TILES];
__device__ __align__(256) int   g_tile_row0[MAX_TILES];
__device__ __align__(256) int   g_tile_nrows[MAX_TILES];
__device__ int   g_num_tiles;

// pure fp16 planes
__device__ __align__(256) __half g_x16[NT*HID];
__device__ __align__(256) __half g_wg16[(size_t)NE*HID*FF];
__device__ __align__(256) __half g_wu16[(size_t)NE*HID*FF];
__device__ __align__(256) __half g_wd16[(size_t)NE*FF*HID];
__device__ __align__(256) __half g_h16[(size_t)NSLOT*FF];
__device__ __align__(256) float g_dout[(size_t)NSLOT*HID];

// ---------------- helpers ---------------------------------------------------
__device__ __forceinline__ uint32_t smem_u32(const void* p) {
    uint32_t a;
    asm("{ .reg .u64 t; cvta.to.shared.u64 t, %1; cvt.u32.u64 %0, t; }" : "=r"(a) : "l"(p));
    return a;
}
__device__ __forceinline__ void cp16(uint32_t dst, const void* src) {
    asm volatile("cp.async.cg.shared.global [%0], [%1], 16;"
        :: "r"(dst), "l"(__cvta_generic_to_global(src)) : "memory");
}
#define CP_COMMIT() asm volatile("cp.async.commit_group;" ::: "memory")
#define CP_WAIT0()  asm volatile("cp.async.wait_group 0;" ::: "memory")

__device__ __forceinline__ void ldsm4(uint32_t* r, uint32_t addr) {
    asm volatile("ldmatrix.sync.aligned.m8n8.x4.shared.b16 {%0,%1,%2,%3}, [%4];"
        : "=r"(r[0]), "=r"(r[1]), "=r"(r[2]), "=r"(r[3]) : "r"(addr));
}
__device__ __forceinline__ void ldsm4t(uint32_t* r, uint32_t addr) {
    asm volatile("ldmatrix.sync.aligned.m8n8.x4.trans.shared.b16 {%0,%1,%2,%3}, [%4];"
        : "=r"(r[0]), "=r"(r[1]), "=r"(r[2]), "=r"(r[3]) : "r"(addr));
}
__device__ __forceinline__ void mma16816(float* d, const uint32_t* a, const uint32_t* b) {
    asm volatile("mma.sync.aligned.m16n8k16.row.col.f32.f16.f16.f32 "
        "{%0,%1,%2,%3}, {%4,%5,%6,%7}, {%8,%9}, {%0,%1,%2,%3};"
        : "+f"(d[0]), "+f"(d[1]), "+f"(d[2]), "+f"(d[3])
        : "r"(a[0]), "r"(a[1]), "r"(a[2]), "r"(a[3]), "r"(b[0]), "r"(b[1]));
}
__device__ __forceinline__ uint32_t pack_h2(float a, float b) {
    unsigned short lo = __half_as_ushort(__float2half_rn(a));
    unsigned short hi = __half_as_ushort(__float2half_rn(b));
    return (uint32_t)lo | ((uint32_t)hi << 16);
}

// SMEM strides (bytes): all row steps == 4 mod 32 banks -> ldmatrix conflict-free
#define A1_STRIDE 272   // GEMM1 A: 256B data (128 fp16 = KC1) + 16B pad
#define B1_STRIDE 144   // GEMM1 B: 128B data (64 fp16 = BN) + 16B pad
#define A2_STRIDE 144   // GEMM2 A: 128B data (64 fp16 = KC2) + 16B pad
#define B2_STRIDE 272   // GEMM2 B: 256B data (128 fp16 = BN2) + 16B pad

#define KC1 128
#define KC2 64
#define A1_PLANE (BM*A1_STRIDE)           // 34816
#define B1_PLANE (KC1*B1_STRIDE)          // 18432
#define A2_PLANE (BM*A2_STRIDE)           // 18432
#define G1_SMEM  (A1_PLANE + 2*B1_PLANE)      // 71680
#define G2_SMEM  (A2_PLANE + KC2*B2_STRIDE)   // 35840

// ---------------- converts --------------------------------------------------
__global__ void convert_x_kernel(const float* __restrict__ src)
{
    size_t i = (size_t)blockIdx.x * blockDim.x + threadIdx.x;   // float4 index
    float4 v = *(const float4*)(src + i * 4);
    *(uint2*)(g_x16 + i*4) = make_uint2(pack_h2(v.x, v.y), pack_h2(v.z, v.w));
}

// one launch converts all three weight tensors (blockIdx.y selects)
__global__ void convert_w_kernel(const float* __restrict__ wg,
                                 const float* __restrict__ wu,
                                 const float* __restrict__ wd)
{
    const float* src = (blockIdx.y == 0) ? wg : (blockIdx.y == 1) ? wu : wd;
    __half* dst = (blockIdx.y == 0) ? g_wg16 : (blockIdx.y == 1) ? g_wu16 : g_wd16;
    size_t i = (size_t)blockIdx.x * blockDim.x + threadIdx.x;
    float4 v = *(const float4*)(src + i * 4);
    *(uint2*)(dst + i*4) = make_uint2(pack_h2(v.x, v.y), pack_h2(v.z, v.w));
}

// ---------------- router ----------------------------------------------------
__global__ void router_kernel(const float* __restrict__ x, const float* __restrict__ gw)
{
    int wid  = (blockIdx.x * blockDim.x + threadIdx.x) >> 5;
    int lane = threadIdx.x & 31;
    if (wid >= NT) return;
    const float* xr = x + (size_t)wid * HID;
    float acc[NE];
    #pragma unroll
    for (int e = 0; e < NE; e++) acc[e] = 0.f;
    for (int h = lane; h < HID; h += 32) {
        float  xv = xr[h];
        float4 a  = *(const float4*)(gw + h*NE);
        float4 b  = *(const float4*)(gw + h*NE + 4);
        acc[0] += xv*a.x; acc[1] += xv*a.y; acc[2] += xv*a.z; acc[3] += xv*a.w;
        acc[4] += xv*b.x; acc[5] += xv*b.y; acc[6] += xv*b.z; acc[7] += xv*b.w;
    }
    #pragma unroll
    for (int e = 0; e < NE; e++)
        #pragma unroll
        for (int o = 16; o > 0; o >>= 1)
            acc[e] += __shfl_xor_sync(0xffffffffu, acc[e], o);
    if (lane == 0) {
        float m = acc[0];
        #pragma unroll
        for (int e = 1; e < NE; e++) m = fmaxf(m, acc[e]);
        float p[NE], s = 0.f;
        #pragma unroll
        for (int e = 0; e < NE; e++) { p[e] = expf(acc[e] - m); s += p[e]; }
        float inv = 1.f / s;
        #pragma unroll
        for (int e = 0; e < NE; e++) p[e] *= inv;
        int i0 = 0;
        #pragma unroll
        for (int e = 1; e < NE; e++) if (p[e] > p[i0]) i0 = e;
        int i1 = (i0 == 0) ? 1 : 0;
        #pragma unroll
        for (int e = 0; e < NE; e++) if (e != i0 && p[e] > p[i1]) i1 = e;
        float w0 = 1.f / (1.f + expf(p[i1] - p[i0]));
        g_top_i[wid*2]   = i0;  g_top_i[wid*2+1] = i1;
        g_top_w[wid*2]   = w0;  g_top_w[wid*2+1] = 1.f - w0;
    }
}

// ---------------- routing build (deterministic) ------------------------------
__global__ void route_build_kernel()
{
    __shared__ int counts[NE];
    __shared__ int offsets[NE+1];
    const int tid  = threadIdx.x;
    const int warp = tid >> 5;
    const int lane = tid & 31;
    int c = 0;
    for (int p = lane; p < NSLOT; p += 32)
        if (g_top_i[p] == warp) c++;
    #pragma unroll
    for (int o = 16; o > 0; o >>= 1) c += __shfl_down_sync(0xffffffffu, c, o);
    if (lane == 0) counts[warp] = c;
    __syncthreads();
    if (tid == 0) {
        int s = 0;
        for (int e = 0; e < NE; e++) { offsets[e] = s; s += counts[e]; }
        offsets[NE] = s;
    }
    __syncthreads();
    int base = offsets[warp];
    for (int p0 = 0; p0 < NSLOT; p0 += 32) {
        int p = p0 + lane;
        bool f = (g_top_i[p] == warp);
        unsigned msk = __ballot_sync(0xffffffffu, f);
        if (f) {
            int slot = base + __popc(msk & ((1u << lane) - 1u));
            g_slot_token[slot] = p >> 1;
            g_token_slot[p]    = slot;
        }
        base += __popc(msk);
    }
    __syncthreads();
    if (tid == 0) {
        int nt = 0;
        for (int e = 0; e < NE; e++) {
            int cnt = counts[e];
            for (int r = 0; r < cnt; r += BM) {
                g_tile_e[nt] = e;
                g_tile_row0[nt] = offsets[e] + r;
                g_tile_nrows[nt] = min(BM, cnt - r);
                nt++;
            }
        }
        g_num_tiles = nt;
    }
}

// ---------------- GEMM1: pure fp16, gate+up, KC=128, fused SwiGLU -----------
__global__ void __launch_bounds__(256) gemm1_kernel()
{
    const int tile = blockIdx.x;
    if (tile >= g_num_tiles) return;
    const int e     = g_tile_e[tile];
    const int row0  = g_tile_row0[tile];
    const int nrows = g_tile_nrows[tile];
    const int n0    = blockIdx.y * BN;

    extern __shared__ __align__(16) char sm[];
    __shared__ int stok[BM];

    const int tid = threadIdx.x, lane = tid & 31, wid = tid >> 5;
    const int warpM = wid & 3, warpN = wid >> 2;

    if (tid < BM) stok[tid] = (tid < nrows) ? g_slot_token[row0 + tid] : 0;
    __syncthreads();

    const __half* bsrc[2] = {
        g_wg16 + (size_t)e*HID*FF, g_wu16 + (size_t)e*HID*FF };

    const uint32_t sa = smem_u32(sm);
    const uint32_t sbb = sa + A1_PLANE;

    float ag[2][4][4], au[2][4][4];
    #pragma unroll
    for (int i = 0; i < 2; i++)
        #pragma unroll
        for (int g = 0; g < 4; g++)
            #pragma unroll
            for (int r = 0; r < 4; r++) { ag[i][g][r] = 0.f; au[i][g][r] = 0.f; }

    for (int ch = 0; ch < HID/KC1; ch++) {     // 8 chunks
        const int k0 = ch * KC1;
        // A: 128 rows x 16 segs = 2048 cp16
        #pragma unroll
        for (int t = 0; t < 8; t++) {
            int idx = tid + t*256;
            int row = idx >> 4, seg = idx & 15;
            cp16(sa + row*A1_STRIDE + seg*16,
                 g_x16 + (size_t)stok[row]*HID + k0 + seg*8);
        }
        // B: 2 mats x 128 k-rows x 8 segs = 2048 cp16
        #pragma unroll
        for (int t = 0; t < 8; t++) {
            int idx = tid + t*256;
            int p = idx >> 10, row = (idx >> 3) & 127, seg = idx & 7;
            cp16(sbb + p*B1_PLANE + row*B1_STRIDE + seg*16,
                 bsrc[p] + (size_t)(k0+row)*FF + n0 + seg*8);
        }
        CP_COMMIT(); CP_WAIT0();
        __syncthreads();

        #pragma unroll
        for (int kk = 0; kk < 8; kk++) {
            uint32_t af[2][4];       // [i]
            #pragma unroll
            for (int i = 0; i < 2; i++) {
                uint32_t ar = (uint32_t)(warpM*32 + i*16 + (lane & 15))*A1_STRIDE
                              + kk*32 + (lane >> 4)*16;
                ldsm4(af[i], sa + ar);
            }
            uint32_t br = (uint32_t)(kk*16 + (lane & 15))*B1_STRIDE
                          + warpN*64 + (lane >> 4)*16;
            uint32_t bf[2][4][2];    // [mat: gate/up][ngroup]
            #pragma unroll
            for (int p = 0; p < 2; p++) {
                uint32_t q0[4], q1[4];
                ldsm4t(q0, sbb + p*B1_PLANE + br);
                ldsm4t(q1, sbb + p*B1_PLANE + br + 32);
                bf[p][0][0]=q0[0]; bf[p][0][1]=q0[1];
                bf[p][1][0]=q0[2]; bf[p][1][1]=q0[3];
                bf[p][2][0]=q1[0]; bf[p][2][1]=q1[1];
                bf[p][3][0]=q1[2]; bf[p][3][1]=q1[3];
            }
            #pragma unroll
            for (int i = 0; i < 2; i++)
                #pragma unroll
                for (int g = 0; g < 4; g++) {
                    mma16816(ag[i][g], af[i], bf[0][g]);
                    mma16816(au[i][g], af[i], bf[1][g]);
                }
        }
        __syncthreads();
    }

    const int qr = lane >> 2;
    const int qc = 2 * (lane & 3);
    #pragma unroll
    for (int i = 0; i < 2; i++)
        #pragma unroll
        for (int g = 0; g < 4; g++) {
            int col = n0 + warpN*32 + g*8 + qc;
            #pragma unroll
            for (int half = 0; half < 2; half++) {
                int tm = warpM*32 + i*16 + qr + half*8;
                if (tm < nrows) {
                    float g0 = ag[i][g][half*2],   u0 = au[i][g][half*2];
                    float g1 = ag[i][g][half*2+1], u1 = au[i][g][half*2+1];
                    float v0 = (g0 / (1.f + __expf(-g0))) * u0;
                    float v1 = (g1 / (1.f + __expf(-g1))) * u1;
                    size_t off = (size_t)(row0 + tm) * FF + col;
                    *(uint32_t*)(g_h16 + off) = pack_h2(v0, v1);
                }
            }
        }
}

// ---------------- GEMM2: pure fp16 down-proj, BN=128, KC=64 -----------------
#define BN2 128
__global__ void __launch_bounds__(256) gemm2_kernel()
{
    const int tile = blockIdx.x;
    if (tile >= g_num_tiles) return;
    const int e     = g_tile_e[tile];
    const int row0  = g_tile_row0[tile];
    const int nrows = g_tile_nrows[tile];
    const int n0    = blockIdx.y * BN2;

    extern __shared__ __align__(16) char sm[];

    const int tid = threadIdx.x, lane = tid & 31, wid = tid >> 5;
    const int warpM = wid & 3, warpN = wid >> 2;           // warpN covers 64 cols

    const __half* bsrc = g_wd16 + (size_t)e*FF*HID;

    const uint32_t sa = smem_u32(sm);
    const uint32_t sbb = sa + A2_PLANE;

    float acc[2][8][4];
    #pragma unroll
    for (int i = 0; i < 2; i++)
        #pragma unroll
        for (int g = 0; g < 8; g++)
            #pragma unroll
            for (int r = 0; r < 4; r++) acc[i][g][r] = 0.f;

    for (int ch = 0; ch < FF/KC2; ch++) {      // 64 chunks
        const int k0 = ch * KC2;
        // A: 128 rows x 8 segs = 1024 cp16
        #pragma unroll
        for (int t = 0; t < 4; t++) {
            int idx = tid + t*256;
            int row = idx >> 3, seg = idx & 7;
            int r = row0 + row; if (r > NSLOT-1) r = NSLOT-1;
            cp16(sa + row*A2_STRIDE + seg*16,
                 g_h16 + (size_t)r*FF + k0 + seg*8);
        }
        // B: 64 k-rows x 16 segs = 1024 cp16
        #pragma unroll
        for (int t = 0; t < 4; t++) {
            int idx = tid + t*256;
            int row = idx >> 4, seg = idx & 15;
            cp16(sbb + row*B2_STRIDE + seg*16,
                 bsrc + (size_t)(k0+row)*HID + n0 + seg*8);
        }
        CP_COMMIT(); CP_WAIT0();
        __syncthreads();

        #pragma unroll
        for (int kk = 0; kk < 4; kk++) {
            uint32_t af[2][4];
            #pragma unroll
            for (int i = 0; i < 2; i++) {
                uint32_t ar = (uint32_t)(warpM*32 + i*16 + (lane & 15))*A2_STRIDE
                              + kk*32 + (lane >> 4)*16;
                ldsm4(af[i], sa + ar);
            }
            uint32_t br = (uint32_t)(kk*16 + (lane & 15))*B2_STRIDE
                          + warpN*128 + (lane >> 4)*16;
            uint32_t bf[8][2];
            #pragma unroll
            for (int q = 0; q < 4; q++) {
                uint32_t qq[4];
                ldsm4t(qq, sbb + br + q*32);
                bf[2*q  ][0]=qq[0]; bf[2*q  ][1]=qq[1];
                bf[2*q+1][0]=qq[2]; bf[2*q+1][1]=qq[3];
            }
            #pragma unroll
            for (int i = 0; i < 2; i++)
                #pragma unroll
                for (int g = 0; g < 8; g++)
                    mma16816(acc[i][g], af[i], bf[g]);
        }
        __syncthreads();
    }

    const int qr = lane >> 2;
    const int qc = 2 * (lane & 3);
    #pragma unroll
    for (int i = 0; i < 2; i++)
        #pragma unroll
        for (int g = 0; g < 8; g++) {
            int col = n0 + warpN*64 + g*8 + qc;   // byte offset 128 == 64 columns
            #pragma unroll
            for (int half = 0; half < 2; half++) {
                int tm = warpM*32 + i*16 + qr + half*8;
                if (tm < nrows) {
                    float2 v = make_float2(acc[i][g][half*2], acc[i][g][half*2+1]);
                    *(float2*)(g_dout + (size_t)(row0 + tm)*HID + col) = v;
                }
            }
        }
}

// ---------------- combine ----------------------------------------------------
__global__ void combine_kernel(float* __restrict__ out)
{
    const int t  = blockIdx.x;
    const int s0 = g_token_slot[t*2];
    const int s1 = g_token_slot[t*2+1];
    const float w0 = g_top_w[t*2];
    const float w1 = g_top_w[t*2+1];
    const int h = threadIdx.x << 2;
    float4 d0 = *(const float4*)(g_dout + (size_t)s0*HID + h);
    float4 d1 = *(const float4*)(g_dout + (size_t)s1*HID + h);
    float4 o;
    o.x = w0*d0.x + w1*d1.x;
    o.y = w0*d0.y + w1*d1.y;
    o.z = w0*d0.z + w1*d1.z;
    o.w = w0*d0.w + w1*d1.w;
    *(float4*)(out + (size_t)t*HID + h) = o;
}

// ---------------------------------------------------------------------------
extern "C" void kernel_launch(void* const* d_in, const int* in_sizes, int n_in,
                              void* d_out, int out_size)
{
    const float* x      = (const float*)d_in[0];
    const float* gate_w = (const float*)d_in[1];
    const float* w_gate = (const float*)d_in[2];
    const float* w_up   = (const float*)d_in[3];
    const float* w_down = (const float*)d_in[4];
    float* out = (float*)d_out;

    static int attr_done = 0;
    if (!attr_done) {
        cudaFuncSetAttribute(gemm1_kernel, cudaFuncAttributeMaxDynamicSharedMemorySize, G1_SMEM);
        cudaFuncSetAttribute(gemm2_kernel, cudaFuncAttributeMaxDynamicSharedMemorySize, G2_SMEM);
        attr_done = 1;
    }

    router_kernel<<<NT*32/256, 256>>>(x, gate_w);
    route_build_kernel<<<1, 256>>>();
    convert_x_kernel<<<(NT*HID/4)/256, 256>>>(x);
    {
        dim3 gw((NE*HID*FF/4)/256, 3);
        convert_w_kernel<<<gw, 256>>>(w_gate, w_up, w_down);
    }
    dim3 g1(MAX_TILES, FF/BN);     // 40 x 64
    gemm1_kernel<<<g1, 256, G1_SMEM>>>();
    dim3 g2(MAX_TILES, HID/BN2);   // 40 x 8
    gemm2_kernel<<<g2, 256, G2_SMEM>>>();
    combine_kernel<<<NT, 256>>>(out);
}

// round 15
// speedup vs baseline: 2.5149x; 1.0010x over previous
#include <cuda_runtime.h>
#include <cuda_fp16.h>
#include <math.h>
#include <stdint.h>

#define HID   1024
#define FF    4096
#define NE    8
#define NT    2048
#define NSLOT (NT*2)
#define BM    128
#define BN    64
#define MAX_TILES 40

// ---------------- scratch (static device globals; no allocation) ------------
__device__ __align__(256) int   g_top_i[NT*2];
__device__ __align__(256) float g_top_w[NT*2];
__device__ __align__(256) int   g_slot_token[NSLOT];
__device__ __align__(256) int   g_token_slot[NT*2];
__device__ __align__(256) int   g_tile_e[MAX_TILES];
__device__ __align__(256) int   g_tile_row0[MAX_TILES];
__device__ __align__(256) int   g_tile_nrows[MAX_TILES];
__device__ int   g_num_tiles;

// pure fp16 planes
__device__ __align__(256) __half g_x16[NT*HID];
__device__ __align__(256) __half g_wg16[(size_t)NE*HID*FF];
__device__ __align__(256) __half g_wu16[(size_t)NE*HID*FF];
__device__ __align__(256) __half g_wd16[(size_t)NE*FF*HID];
__device__ __align__(256) __half g_h16[(size_t)NSLOT*FF];
__device__ __align__(256) float g_dout[(size_t)NSLOT*HID];

// ---------------- helpers ---------------------------------------------------
__device__ __forceinline__ uint32_t smem_u32(const void* p) {
    uint32_t a;
    asm("{ .reg .u64 t; cvta.to.shared.u64 t, %1; cvt.u32.u64 %0, t; }" : "=r"(a) : "l"(p));
    return a;
}
__device__ __forceinline__ void cp16(uint32_t dst, const void* src) {
    asm volatile("cp.async.cg.shared.global [%0], [%1], 16;"
        :: "r"(dst), "l"(__cvta_generic_to_global(src)) : "memory");
}
#define CP_COMMIT() asm volatile("cp.async.commit_group;" ::: "memory")
#define CP_WAIT0()  asm volatile("cp.async.wait_group 0;" ::: "memory")

__device__ __forceinline__ void ldsm4(uint32_t* r, uint32_t addr) {
    asm volatile("ldmatrix.sync.aligned.m8n8.x4.shared.b16 {%0,%1,%2,%3}, [%4];"
        : "=r"(r[0]), "=r"(r[1]), "=r"(r[2]), "=r"(r[3]) : "r"(addr));
}
__device__ __forceinline__ void ldsm4t(uint32_t* r, uint32_t addr) {
    asm volatile("ldmatrix.sync.aligned.m8n8.x4.trans.shared.b16 {%0,%1,%2,%3}, [%4];"
        : "=r"(r[0]), "=r"(r[1]), "=r"(r[2]), "=r"(r[3]) : "r"(addr));
}
__device__ __forceinline__ void mma16816(float* d, const uint32_t* a, const uint32_t* b) {
    asm volatile("mma.sync.aligned.m16n8k16.row.col.f32.f16.f16.f32 "
        "{%0,%1,%2,%3}, {%4,%5,%6,%7}, {%8,%9}, {%0,%1,%2,%3};"
        : "+f"(d[0]), "+f"(d[1]), "+f"(d[2]), "+f"(d[3])
        : "r"(a[0]), "r"(a[1]), "r"(a[2]), "r"(a[3]), "r"(b[0]), "r"(b[1]));
}
__device__ __forceinline__ uint32_t pack_h2(float a, float b) {
    unsigned short lo = __half_as_ushort(__float2half_rn(a));
    unsigned short hi = __half_as_ushort(__float2half_rn(b));
    return (uint32_t)lo | ((uint32_t)hi << 16);
}

// SMEM strides (bytes): all row steps == 4 mod 32 banks -> ldmatrix conflict-free
#define A1_STRIDE 272   // GEMM1 A: 256B data (128 fp16 = KC1) + 16B pad
#define B1_STRIDE 144   // GEMM1 B: 128B data (64 fp16 = BN) + 16B pad
#define A2_STRIDE 272   // GEMM2 A: 256B data (128 fp16 = KC2) + 16B pad
#define B2_STRIDE 272   // GEMM2 B: 256B data (128 fp16 = BN2) + 16B pad

#define KC1 128
#define KC2 128
#define A1_PLANE (BM*A1_STRIDE)           // 34816
#define B1_PLANE (KC1*B1_STRIDE)          // 18432
#define A2_PLANE (BM*A2_STRIDE)           // 34816
#define G1_SMEM  (A1_PLANE + 2*B1_PLANE)      // 71680
#define G2_SMEM  (A2_PLANE + KC2*B2_STRIDE)   // 69632

// ---------------- converts --------------------------------------------------
__global__ void convert_x_kernel(const float* __restrict__ src)
{
    size_t i = (size_t)blockIdx.x * blockDim.x + threadIdx.x;   // float4 index
    float4 v = *(const float4*)(src + i * 4);
    *(uint2*)(g_x16 + i*4) = make_uint2(pack_h2(v.x, v.y), pack_h2(v.z, v.w));
}

// one launch converts all three weight tensors (blockIdx.y selects)
__global__ void convert_w_kernel(const float* __restrict__ wg,
                                 const float* __restrict__ wu,
                                 const float* __restrict__ wd)
{
    const float* src = (blockIdx.y == 0) ? wg : (blockIdx.y == 1) ? wu : wd;
    __half* dst = (blockIdx.y == 0) ? g_wg16 : (blockIdx.y == 1) ? g_wu16 : g_wd16;
    size_t i = (size_t)blockIdx.x * blockDim.x + threadIdx.x;
    float4 v = *(const float4*)(src + i * 4);
    *(uint2*)(dst + i*4) = make_uint2(pack_h2(v.x, v.y), pack_h2(v.z, v.w));
}

// ---------------- router ----------------------------------------------------
__global__ void router_kernel(const float* __restrict__ x, const float* __restrict__ gw)
{
    int wid  = (blockIdx.x * blockDim.x + threadIdx.x) >> 5;
    int lane = threadIdx.x & 31;
    if (wid >= NT) return;
    const float* xr = x + (size_t)wid * HID;
    float acc[NE];
    #pragma unroll
    for (int e = 0; e < NE; e++) acc[e] = 0.f;
    for (int h = lane; h < HID; h += 32) {
        float  xv = xr[h];
        float4 a  = *(const float4*)(gw + h*NE);
        float4 b  = *(const float4*)(gw + h*NE + 4);
        acc[0] += xv*a.x; acc[1] += xv*a.y; acc[2] += xv*a.z; acc[3] += xv*a.w;
        acc[4] += xv*b.x; acc[5] += xv*b.y; acc[6] += xv*b.z; acc[7] += xv*b.w;
    }
    #pragma unroll
    for (int e = 0; e < NE; e++)
        #pragma unroll
        for (int o = 16; o > 0; o >>= 1)
            acc[e] += __shfl_xor_sync(0xffffffffu, acc[e], o);
    if (lane == 0) {
        float m = acc[0];
        #pragma unroll
        for (int e = 1; e < NE; e++) m = fmaxf(m, acc[e]);
        float p[NE], s = 0.f;
        #pragma unroll
        for (int e = 0; e < NE; e++) { p[e] = expf(acc[e] - m); s += p[e]; }
        float inv = 1.f / s;
        #pragma unroll
        for (int e = 0; e < NE; e++) p[e] *= inv;
        int i0 = 0;
        #pragma unroll
        for (int e = 1; e < NE; e++) if (p[e] > p[i0]) i0 = e;
        int i1 = (i0 == 0) ? 1 : 0;
        #pragma unroll
        for (int e = 0; e < NE; e++) if (e != i0 && p[e] > p[i1]) i1 = e;
        float w0 = 1.f / (1.f + expf(p[i1] - p[i0]));
        g_top_i[wid*2]   = i0;  g_top_i[wid*2+1] = i1;
        g_top_w[wid*2]   = w0;  g_top_w[wid*2+1] = 1.f - w0;
    }
}

// ---------------- routing build (deterministic) ------------------------------
__global__ void route_build_kernel()
{
    __shared__ int counts[NE];
    __shared__ int offsets[NE+1];
    const int tid  = threadIdx.x;
    const int warp = tid >> 5;
    const int lane = tid & 31;
    int c = 0;
    for (int p = lane; p < NSLOT; p += 32)
        if (g_top_i[p] == warp) c++;
    #pragma unroll
    for (int o = 16; o > 0; o >>= 1) c += __shfl_down_sync(0xffffffffu, c, o);
    if (lane == 0) counts[warp] = c;
    __syncthreads();
    if (tid == 0) {
        int s = 0;
        for (int e = 0; e < NE; e++) { offsets[e] = s; s += counts[e]; }
        offsets[NE] = s;
    }
    __syncthreads();
    int base = offsets[warp];
    for (int p0 = 0; p0 < NSLOT; p0 += 32) {
        int p = p0 + lane;
        bool f = (g_top_i[p] == warp);
        unsigned msk = __ballot_sync(0xffffffffu, f);
        if (f) {
            int slot = base + __popc(msk & ((1u << lane) - 1u));
            g_slot_token[slot] = p >> 1;
            g_token_slot[p]    = slot;
        }
        base += __popc(msk);
    }
    __syncthreads();
    if (tid == 0) {
        int nt = 0;
        for (int e = 0; e < NE; e++) {
            int cnt = counts[e];
            for (int r = 0; r < cnt; r += BM) {
                g_tile_e[nt] = e;
                g_tile_row0[nt] = offsets[e] + r;
                g_tile_nrows[nt] = min(BM, cnt - r);
                nt++;
            }
        }
        g_num_tiles = nt;
    }
}

// ---------------- GEMM1: pure fp16, gate+up, KC=128, fused SwiGLU -----------
__global__ void __launch_bounds__(256) gemm1_kernel()
{
    const int tile = blockIdx.x;
    if (tile >= g_num_tiles) return;
    const int e     = g_tile_e[tile];
    const int row0  = g_tile_row0[tile];
    const int nrows = g_tile_nrows[tile];
    const int n0    = blockIdx.y * BN;

    extern __shared__ __align__(16) char sm[];
    __shared__ int stok[BM];

    const int tid = threadIdx.x, lane = tid & 31, wid = tid >> 5;
    const int warpM = wid & 3, warpN = wid >> 2;

    if (tid < BM) stok[tid] = (tid < nrows) ? g_slot_token[row0 + tid] : 0;
    __syncthreads();

    const __half* bsrc[2] = {
        g_wg16 + (size_t)e*HID*FF, g_wu16 + (size_t)e*HID*FF };

    const uint32_t sa = smem_u32(sm);
    const uint32_t sbb = sa + A1_PLANE;

    float ag[2][4][4], au[2][4][4];
    #pragma unroll
    for (int i = 0; i < 2; i++)
        #pragma unroll
        for (int g = 0; g < 4; g++)
            #pragma unroll
            for (int r = 0; r < 4; r++) { ag[i][g][r] = 0.f; au[i][g][r] = 0.f; }

    for (int ch = 0; ch < HID/KC1; ch++) {     // 8 chunks
        const int k0 = ch * KC1;
        // A: 128 rows x 16 segs = 2048 cp16
        #pragma unroll
        for (int t = 0; t < 8; t++) {
            int idx = tid + t*256;
            int row = idx >> 4, seg = idx & 15;
            cp16(sa + row*A1_STRIDE + seg*16,
                 g_x16 + (size_t)stok[row]*HID + k0 + seg*8);
        }
        // B: 2 mats x 128 k-rows x 8 segs = 2048 cp16
        #pragma unroll
        for (int t = 0; t < 8; t++) {
            int idx = tid + t*256;
            int p = idx >> 10, row = (idx >> 3) & 127, seg = idx & 7;
            cp16(sbb + p*B1_PLANE + row*B1_STRIDE + seg*16,
                 bsrc[p] + (size_t)(k0+row)*FF + n0 + seg*8);
        }
        CP_COMMIT(); CP_WAIT0();
        __syncthreads();

        #pragma unroll
        for (int kk = 0; kk < 8; kk++) {
            uint32_t af[2][4];       // [i]
            #pragma unroll
            for (int i = 0; i < 2; i++) {
                uint32_t ar = (uint32_t)(warpM*32 + i*16 + (lane & 15))*A1_STRIDE
                              + kk*32 + (lane >> 4)*16;
                ldsm4(af[i], sa + ar);
            }
            uint32_t br = (uint32_t)(kk*16 + (lane & 15))*B1_STRIDE
                          + warpN*64 + (lane >> 4)*16;
            uint32_t bf[2][4][2];    // [mat: gate/up][ngroup]
            #pragma unroll
            for (int p = 0; p < 2; p++) {
                uint32_t q0[4], q1[4];
                ldsm4t(q0, sbb + p*B1_PLANE + br);
                ldsm4t(q1, sbb + p*B1_PLANE + br + 32);
                bf[p][0][0]=q0[0]; bf[p][0][1]=q0[1];
                bf[p][1][0]=q0[2]; bf[p][1][1]=q0[3];
                bf[p][2][0]=q1[0]; bf[p][2][1]=q1[1];
                bf[p][3][0]=q1[2]; bf[p][3][1]=q1[3];
            }
            #pragma unroll
            for (int i = 0; i < 2; i++)
                #pragma unroll
                for (int g = 0; g < 4; g++) {
                    mma16816(ag[i][g], af[i], bf[0][g]);
                    mma16816(au[i][g], af[i], bf[1][g]);
                }
        }
        __syncthreads();
    }

    const int qr = lane >> 2;
    const int qc = 2 * (lane & 3);
    #pragma unroll
    for (int i = 0; i < 2; i++)
        #pragma unroll
        for (int g = 0; g < 4; g++) {
            int col = n0 + warpN*32 + g*8 + qc;
            #pragma unroll
            for (int half = 0; half < 2; half++) {
                int tm = warpM*32 + i*16 + qr + half*8;
                if (tm < nrows) {
                    float g0 = ag[i][g][half*2],   u0 = au[i][g][half*2];
                    float g1 = ag[i][g][half*2+1], u1 = au[i][g][half*2+1];
                    float v0 = (g0 / (1.f + __expf(-g0))) * u0;
                    float v1 = (g1 / (1.f + __expf(-g1))) * u1;
                    size_t off = (size_t)(row0 + tm) * FF + col;
                    *(uint32_t*)(g_h16 + off) = pack_h2(v0, v1);
                }
            }
        }
}

// ---------------- GEMM2: pure fp16 down-proj, BN=128, KC=128 ----------------
#define BN2 128
__global__ void __launch_bounds__(256) gemm2_kernel()
{
    const int tile = blockIdx.x;
    if (tile >= g_num_tiles) return;
    const int e     = g_tile_e[tile];
    const int row0  = g_tile_row0[tile];
    const int nrows = g_tile_nrows[tile];
    const int n0    = blockIdx.y * BN2;

    extern __shared__ __align__(16) char sm[];

    const int tid = threadIdx.x, lane = tid & 31, wid = tid >> 5;
    const int warpM = wid & 3, warpN = wid >> 2;           // warpN covers 64 cols

    const __half* bsrc = g_wd16 + (size_t)e*FF*HID;

    const uint32_t sa = smem_u32(sm);
    const uint32_t sbb = sa + A2_PLANE;

    float acc[2][8][4];
    #pragma unroll
    for (int i = 0; i < 2; i++)
        #pragma unroll
        for (int g = 0; g < 8; g++)
            #pragma unroll
            for (int r = 0; r < 4; r++) acc[i][g][r] = 0.f;

    for (int ch = 0; ch < FF/KC2; ch++) {      // 32 chunks
        const int k0 = ch * KC2;
        // A: 128 rows x 16 segs = 2048 cp16
        #pragma unroll
        for (int t = 0; t < 8; t++) {
            int idx = tid + t*256;
            int row = idx >> 4, seg = idx & 15;
            int r = row0 + row; if (r > NSLOT-1) r = NSLOT-1;
            cp16(sa + row*A2_STRIDE + seg*16,
                 g_h16 + (size_t)r*FF + k0 + seg*8);
        }
        // B: 128 k-rows x 16 segs = 2048 cp16
        #pragma unroll
        for (int t = 0; t < 8; t++) {
            int idx = tid + t*256;
            int row = idx >> 4, seg = idx & 15;
            cp16(sbb + row*B2_STRIDE + seg*16,
                 bsrc + (size_t)(k0+row)*HID + n0 + seg*8);
        }
        CP_COMMIT(); CP_WAIT0();
        __syncthreads();

        #pragma unroll
        for (int kk = 0; kk < 8; kk++) {
            uint32_t af[2][4];
            #pragma unroll
            for (int i = 0; i < 2; i++) {
                uint32_t ar = (uint32_t)(warpM*32 + i*16 + (lane & 15))*A2_STRIDE
                              + kk*32 + (lane >> 4)*16;
                ldsm4(af[i], sa + ar);
            }
            uint32_t br = (uint32_t)(kk*16 + (lane & 15))*B2_STRIDE
                          + warpN*128 + (lane >> 4)*16;
            uint32_t bf[8][2];
            #pragma unroll
            for (int q = 0; q < 4; q++) {
                uint32_t qq[4];
                ldsm4t(qq, sbb + br + q*32);
                bf[2*q  ][0]=qq[0]; bf[2*q  ][1]=qq[1];
                bf[2*q+1][0]=qq[2]; bf[2*q+1][1]=qq[3];
            }
            #pragma unroll
            for (int i = 0; i < 2; i++)
                #pragma unroll
                for (int g = 0; g < 8; g++)
                    mma16816(acc[i][g], af[i], bf[g]);
        }
        __syncthreads();
    }

    const int qr = lane >> 2;
    const int qc = 2 * (lane & 3);
    #pragma unroll
    for (int i = 0; i < 2; i++)
        #pragma unroll
        for (int g = 0; g < 8; g++) {
            int col = n0 + warpN*64 + g*8 + qc;   // byte offset 128 == 64 columns
            #pragma unroll
            for (int half = 0; half < 2; half++) {
                int tm = warpM*32 + i*16 + qr + half*8;
                if (tm < nrows) {
                    float2 v = make_float2(acc[i][g][half*2], acc[i][g][half*2+1]);
                    *(float2*)(g_dout + (size_t)(row0 + tm)*HID + col) = v;
                }
            }
        }
}

// ---------------- combine ----------------------------------------------------
__global__ void combine_kernel(float* __restrict__ out)
{
    const int t  = blockIdx.x;
    const int s0 = g_token_slot[t*2];
    const int s1 = g_token_slot[t*2+1];
    const float w0 = g_top_w[t*2];
    const float w1 = g_top_w[t*2+1];
    const int h = threadIdx.x << 2;
    float4 d0 = *(const float4*)(g_dout + (size_t)s0*HID + h);
    float4 d1 = *(const float4*)(g_dout + (size_t)s1*HID + h);
    float4 o;
    o.x = w0*d0.x + w1*d1.x;
    o.y = w0*d0.y + w1*d1.y;
    o.z = w0*d0.z + w1*d1.z;
    o.w = w0*d0.w + w1*d1.w;
    *(float4*)(out + (size_t)t*HID + h) = o;
}

// ---------------------------------------------------------------------------
extern "C" void kernel_launch(void* const* d_in, const int* in_sizes, int n_in,
                              void* d_out, int out_size)
{
    const float* x      = (const float*)d_in[0];
    const float* gate_w = (const float*)d_in[1];
    const float* w_gate = (const float*)d_in[2];
    const float* w_up   = (const float*)d_in[3];
    const float* w_down = (const float*)d_in[4];
    float* out = (float*)d_out;

    static int attr_done = 0;
    if (!attr_done) {
        cudaFuncSetAttribute(gemm1_kernel, cudaFuncAttributeMaxDynamicSharedMemorySize, G1_SMEM);
        cudaFuncSetAttribute(gemm2_kernel, cudaFuncAttributeMaxDynamicSharedMemorySize, G2_SMEM);
        attr_done = 1;
    }

    router_kernel<<<NT*32/256, 256>>>(x, gate_w);
    route_build_kernel<<<1, 256>>>();
    convert_x_kernel<<<(NT*HID/4)/256, 256>>>(x);
    {
        dim3 gw((NE*HID*FF/4)/256, 3);
        convert_w_kernel<<<gw, 256>>>(w_gate, w_up, w_down);
    }
    dim3 g1(MAX_TILES, FF/BN);     // 40 x 64
    gemm1_kernel<<<g1, 256, G1_SMEM>>>();
    dim3 g2(MAX_TILES, HID/BN2);   // 40 x 8
    gemm2_kernel<<<g2, 256, G2_SMEM>>>();
    combine_kernel<<<NT, 256>>>(out);
}

// round 16
// speedup vs baseline: 2.5765x; 1.0245x over previous
#include <cuda_runtime.h>
#include <cuda_fp16.h>
#include <math.h>
#include <stdint.h>

#define HID   1024
#define FF    4096
#define NE    8
#define NT    2048
#define NSLOT (NT*2)
#define BM    128
#define BN    64
#define MAX_TILES 40

// ---------------- scratch (static device globals; no allocation) ------------
__device__ __align__(256) int   g_top_i[NT*2];
__device__ __align__(256) float g_top_w[NT*2];
__device__ __align__(256) int   g_slot_token[NSLOT];
__device__ __align__(256) int   g_token_slot[NT*2];
__device__ __align__(256) int   g_tile_e[MAX_TILES];
__device__ __align__(256) int   g_tile_row0[MAX_TILES];
__device__ __align__(256) int   g_tile_nrows[MAX_TILES];
__device__ int   g_num_tiles;

// pure fp16 planes
__device__ __align__(256) __half g_x16[NT*HID];
__device__ __align__(256) __half g_wg16[(size_t)NE*HID*FF];
__device__ __align__(256) __half g_wu16[(size_t)NE*HID*FF];
__device__ __align__(256) __half g_wd16[(size_t)NE*FF*HID];
__device__ __align__(256) __half g_h16[(size_t)NSLOT*FF];
__device__ __align__(256) float g_dout[(size_t)NSLOT*HID];

// ---------------- helpers ---------------------------------------------------
__device__ __forceinline__ uint32_t smem_u32(const void* p) {
    uint32_t a;
    asm("{ .reg .u64 t; cvta.to.shared.u64 t, %1; cvt.u32.u64 %0, t; }" : "=r"(a) : "l"(p));
    return a;
}
__device__ __forceinline__ void cp16(uint32_t dst, const void* src) {
    asm volatile("cp.async.cg.shared.global [%0], [%1], 16;"
        :: "r"(dst), "l"(__cvta_generic_to_global(src)) : "memory");
}
#define CP_COMMIT() asm volatile("cp.async.commit_group;" ::: "memory")
#define CP_WAIT0()  asm volatile("cp.async.wait_group 0;" ::: "memory")

__device__ __forceinline__ void ldsm4(uint32_t* r, uint32_t addr) {
    asm volatile("ldmatrix.sync.aligned.m8n8.x4.shared.b16 {%0,%1,%2,%3}, [%4];"
        : "=r"(r[0]), "=r"(r[1]), "=r"(r[2]), "=r"(r[3]) : "r"(addr));
}
__device__ __forceinline__ void ldsm4t(uint32_t* r, uint32_t addr) {
    asm volatile("ldmatrix.sync.aligned.m8n8.x4.trans.shared.b16 {%0,%1,%2,%3}, [%4];"
        : "=r"(r[0]), "=r"(r[1]), "=r"(r[2]), "=r"(r[3]) : "r"(addr));
}
__device__ __forceinline__ void mma16816(float* d, const uint32_t* a, const uint32_t* b) {
    asm volatile("mma.sync.aligned.m16n8k16.row.col.f32.f16.f16.f32 "
        "{%0,%1,%2,%3}, {%4,%5,%6,%7}, {%8,%9}, {%0,%1,%2,%3};"
        : "+f"(d[0]), "+f"(d[1]), "+f"(d[2]), "+f"(d[3])
        : "r"(a[0]), "r"(a[1]), "r"(a[2]), "r"(a[3]), "r"(b[0]), "r"(b[1]));
}
__device__ __forceinline__ uint32_t pack_h2(float a, float b) {
    unsigned short lo = __half_as_ushort(__float2half_rn(a));
    unsigned short hi = __half_as_ushort(__float2half_rn(b));
    return (uint32_t)lo | ((uint32_t)hi << 16);
}

// SMEM strides (bytes): all row steps == 4 mod 32 banks -> ldmatrix conflict-free
#define A1_STRIDE 272   // GEMM1 A: 256B data (128 fp16 = KC1) + 16B pad
#define B1_STRIDE 144   // GEMM1 B: 128B data (64 fp16 = BN) + 16B pad
#define A2_STRIDE 272   // GEMM2 A: 256B data (128 fp16 = KC2) + 16B pad
#define B2_STRIDE 272   // GEMM2 B: 256B data (128 fp16 = BN2) + 16B pad

#define KC1 128
#define KC2 128
#define A1_PLANE (BM*A1_STRIDE)           // 34816
#define B1_PLANE (KC1*B1_STRIDE)          // 18432
#define A2_PLANE (BM*A2_STRIDE)           // 34816
#define G1_SMEM  (A1_PLANE + 2*B1_PLANE)      // 71680
#define G2_SMEM  (A2_PLANE + KC2*B2_STRIDE)   // 69632

// ---------------- convert: wg + wu only (wd handled inside gemm1 launch) ----
__global__ void convert_w_kernel(const float* __restrict__ wg,
                                 const float* __restrict__ wu)
{
    const float* src = (blockIdx.y == 0) ? wg : wu;
    __half* dst = (blockIdx.y == 0) ? g_wg16 : g_wu16;
    size_t i = (size_t)blockIdx.x * blockDim.x + threadIdx.x;
    float4 v = *(const float4*)(src + i * 4);
    *(uint2*)(dst + i*4) = make_uint2(pack_h2(v.x, v.y), pack_h2(v.z, v.w));
}

// ---------------- router (also emits fp16 x) --------------------------------
__global__ void router_kernel(const float* __restrict__ x, const float* __restrict__ gw)
{
    int wid  = (blockIdx.x * blockDim.x + threadIdx.x) >> 5;
    int lane = threadIdx.x & 31;
    if (wid >= NT) return;
    const float* xr = x + (size_t)wid * HID;
    __half* xo = g_x16 + (size_t)wid * HID;
    float acc[NE];
    #pragma unroll
    for (int e = 0; e < NE; e++) acc[e] = 0.f;
    for (int h = lane; h < HID; h += 32) {
        float  xv = xr[h];
        xo[h] = __float2half_rn(xv);            // fused convert_x
        float4 a  = *(const float4*)(gw + h*NE);
        float4 b  = *(const float4*)(gw + h*NE + 4);
        acc[0] += xv*a.x; acc[1] += xv*a.y; acc[2] += xv*a.z; acc[3] += xv*a.w;
        acc[4] += xv*b.x; acc[5] += xv*b.y; acc[6] += xv*b.z; acc[7] += xv*b.w;
    }
    #pragma unroll
    for (int e = 0; e < NE; e++)
        #pragma unroll
        for (int o = 16; o > 0; o >>= 1)
            acc[e] += __shfl_xor_sync(0xffffffffu, acc[e], o);
    if (lane == 0) {
        float m = acc[0];
        #pragma unroll
        for (int e = 1; e < NE; e++) m = fmaxf(m, acc[e]);
        float p[NE], s = 0.f;
        #pragma unroll
        for (int e = 0; e < NE; e++) { p[e] = expf(acc[e] - m); s += p[e]; }
        float inv = 1.f / s;
        #pragma unroll
        for (int e = 0; e < NE; e++) p[e] *= inv;
        int i0 = 0;
        #pragma unroll
        for (int e = 1; e < NE; e++) if (p[e] > p[i0]) i0 = e;
        int i1 = (i0 == 0) ? 1 : 0;
        #pragma unroll
        for (int e = 0; e < NE; e++) if (e != i0 && p[e] > p[i1]) i1 = e;
        float w0 = 1.f / (1.f + expf(p[i1] - p[i0]));
        g_top_i[wid*2]   = i0;  g_top_i[wid*2+1] = i1;
        g_top_w[wid*2]   = w0;  g_top_w[wid*2+1] = 1.f - w0;
    }
}

// ---------------- routing build (deterministic) ------------------------------
__global__ void route_build_kernel()
{
    __shared__ int counts[NE];
    __shared__ int offsets[NE+1];
    const int tid  = threadIdx.x;
    const int warp = tid >> 5;
    const int lane = tid & 31;
    int c = 0;
    for (int p = lane; p < NSLOT; p += 32)
        if (g_top_i[p] == warp) c++;
    #pragma unroll
    for (int o = 16; o > 0; o >>= 1) c += __shfl_down_sync(0xffffffffu, c, o);
    if (lane == 0) counts[warp] = c;
    __syncthreads();
    if (tid == 0) {
        int s = 0;
        for (int e = 0; e < NE; e++) { offsets[e] = s; s += counts[e]; }
        offsets[NE] = s;
    }
    __syncthreads();
    int base = offsets[warp];
    for (int p0 = 0; p0 < NSLOT; p0 += 32) {
        int p = p0 + lane;
        bool f = (g_top_i[p] == warp);
        unsigned msk = __ballot_sync(0xffffffffu, f);
        if (f) {
            int slot = base + __popc(msk & ((1u << lane) - 1u));
            g_slot_token[slot] = p >> 1;
            g_token_slot[p]    = slot;
        }
        base += __popc(msk);
    }
    __syncthreads();
    if (tid == 0) {
        int nt = 0;
        for (int e = 0; e < NE; e++) {
            int cnt = counts[e];
            for (int r = 0; r < cnt; r += BM) {
                g_tile_e[nt] = e;
                g_tile_row0[nt] = offsets[e] + r;
                g_tile_nrows[nt] = min(BM, cnt - r);
                nt++;
            }
        }
        g_num_tiles = nt;
    }
}

// ---------------- GEMM1 + wd-convert producer blocks ------------------------
// grid (MAX_TILES, 1 + FF/BN): y==0 -> convert w_down (runs concurrently,
// scheduled in wave 1); y>=1 -> gemm tile with n0 = (y-1)*BN.
__global__ void __launch_bounds__(256) gemm1_kernel(const float* __restrict__ wd)
{
    if (blockIdx.y == 0) {
        // producer blocks: grid-stride fp32->fp16 convert of w_down
        const size_t total = (size_t)NE*FF*HID/4;   // float4 count
        for (size_t i = (size_t)blockIdx.x*256 + threadIdx.x; i < total;
             i += (size_t)MAX_TILES*256) {
            float4 v = *(const float4*)(wd + i*4);
            *(uint2*)(g_wd16 + i*4) = make_uint2(pack_h2(v.x, v.y), pack_h2(v.z, v.w));
        }
        return;
    }

    const int tile = blockIdx.x;
    if (tile >= g_num_tiles) return;
    const int e     = g_tile_e[tile];
    const int row0  = g_tile_row0[tile];
    const int nrows = g_tile_nrows[tile];
    const int n0    = (blockIdx.y - 1) * BN;

    extern __shared__ __align__(16) char sm[];
    __shared__ int stok[BM];

    const int tid = threadIdx.x, lane = tid & 31, wid = tid >> 5;
    const int warpM = wid & 3, warpN = wid >> 2;

    if (tid < BM) stok[tid] = (tid < nrows) ? g_slot_token[row0 + tid] : 0;
    __syncthreads();

    const __half* bsrc[2] = {
        g_wg16 + (size_t)e*HID*FF, g_wu16 + (size_t)e*HID*FF };

    const uint32_t sa = smem_u32(sm);
    const uint32_t sbb = sa + A1_PLANE;

    float ag[2][4][4], au[2][4][4];
    #pragma unroll
    for (int i = 0; i < 2; i++)
        #pragma unroll
        for (int g = 0; g < 4; g++)
            #pragma unroll
            for (int r = 0; r < 4; r++) { ag[i][g][r] = 0.f; au[i][g][r] = 0.f; }

    for (int ch = 0; ch < HID/KC1; ch++) {     // 8 chunks
        const int k0 = ch * KC1;
        // A: 128 rows x 16 segs = 2048 cp16
        #pragma unroll
        for (int t = 0; t < 8; t++) {
            int idx = tid + t*256;
            int row = idx >> 4, seg = idx & 15;
            cp16(sa + row*A1_STRIDE + seg*16,
                 g_x16 + (size_t)stok[row]*HID + k0 + seg*8);
        }
        // B: 2 mats x 128 k-rows x 8 segs = 2048 cp16
        #pragma unroll
        for (int t = 0; t < 8; t++) {
            int idx = tid + t*256;
            int p = idx >> 10, row = (idx >> 3) & 127, seg = idx & 7;
            cp16(sbb + p*B1_PLANE + row*B1_STRIDE + seg*16,
                 bsrc[p] + (size_t)(k0+row)*FF + n0 + seg*8);
        }
        CP_COMMIT(); CP_WAIT0();
        __syncthreads();

        #pragma unroll
        for (int kk = 0; kk < 8; kk++) {
            uint32_t af[2][4];       // [i]
            #pragma unroll
            for (int i = 0; i < 2; i++) {
                uint32_t ar = (uint32_t)(warpM*32 + i*16 + (lane & 15))*A1_STRIDE
                              + kk*32 + (lane >> 4)*16;
                ldsm4(af[i], sa + ar);
            }
            uint32_t br = (uint32_t)(kk*16 + (lane & 15))*B1_STRIDE
                          + warpN*64 + (lane >> 4)*16;
            uint32_t bf[2][4][2];    // [mat: gate/up][ngroup]
            #pragma unroll
            for (int p = 0; p < 2; p++) {
                uint32_t q0[4], q1[4];
                ldsm4t(q0, sbb + p*B1_PLANE + br);
                ldsm4t(q1, sbb + p*B1_PLANE + br + 32);
                bf[p][0][0]=q0[0]; bf[p][0][1]=q0[1];
                bf[p][1][0]=q0[2]; bf[p][1][1]=q0[3];
                bf[p][2][0]=q1[0]; bf[p][2][1]=q1[1];
                bf[p][3][0]=q1[2]; bf[p][3][1]=q1[3];
            }
            #pragma unroll
            for (int i = 0; i < 2; i++)
                #pragma unroll
                for (int g = 0; g < 4; g++) {
                    mma16816(ag[i][g], af[i], bf[0][g]);
                    mma16816(au[i][g], af[i], bf[1][g]);
                }
        }
        __syncthreads();
    }

    const int qr = lane >> 2;
    const int qc = 2 * (lane & 3);
    #pragma unroll
    for (int i = 0; i < 2; i++)
        #pragma unroll
        for (int g = 0; g < 4; g++) {
            int col = n0 + warpN*32 + g*8 + qc;
            #pragma unroll
            for (int half = 0; half < 2; half++) {
                int tm = warpM*32 + i*16 + qr + half*8;
                if (tm < nrows) {
                    float g0 = ag[i][g][half*2],   u0 = au[i][g][half*2];
                    float g1 = ag[i][g][half*2+1], u1 = au[i][g][half*2+1];
                    float v0 = (g0 / (1.f + __expf(-g0))) * u0;
                    float v1 = (g1 / (1.f + __expf(-g1))) * u1;
                    size_t off = (size_t)(row0 + tm) * FF + col;
                    *(uint32_t*)(g_h16 + off) = pack_h2(v0, v1);
                }
            }
        }
}

// ---------------- GEMM2: pure fp16 down-proj, BN=128, KC=128 ----------------
#define BN2 128
__global__ void __launch_bounds__(256) gemm2_kernel()
{
    const int tile = blockIdx.x;
    if (tile >= g_num_tiles) return;
    const int e     = g_tile_e[tile];
    const int row0  = g_tile_row0[tile];
    const int nrows = g_tile_nrows[tile];
    const int n0    = blockIdx.y * BN2;

    extern __shared__ __align__(16) char sm[];

    const int tid = threadIdx.x, lane = tid & 31, wid = tid >> 5;
    const int warpM = wid & 3, warpN = wid >> 2;           // warpN covers 64 cols

    const __half* bsrc = g_wd16 + (size_t)e*FF*HID;

    const uint32_t sa = smem_u32(sm);
    const uint32_t sbb = sa + A2_PLANE;

    float acc[2][8][4];
    #pragma unroll
    for (int i = 0; i < 2; i++)
        #pragma unroll
        for (int g = 0; g < 8; g++)
            #pragma unroll
            for (int r = 0; r < 4; r++) acc[i][g][r] = 0.f;

    for (int ch = 0; ch < FF/KC2; ch++) {      // 32 chunks
        const int k0 = ch * KC2;
        // A: 128 rows x 16 segs = 2048 cp16
        #pragma unroll
        for (int t = 0; t < 8; t++) {
            int idx = tid + t*256;
            int row = idx >> 4, seg = idx & 15;
            int r = row0 + row; if (r > NSLOT-1) r = NSLOT-1;
            cp16(sa + row*A2_STRIDE + seg*16,
                 g_h16 + (size_t)r*FF + k0 + seg*8);
        }
        // B: 128 k-rows x 16 segs = 2048 cp16
        #pragma unroll
        for (int t = 0; t < 8; t++) {
            int idx = tid + t*256;
            int row = idx >> 4, seg = idx & 15;
            cp16(sbb + row*B2_STRIDE + seg*16,
                 bsrc + (size_t)(k0+row)*HID + n0 + seg*8);
        }
        CP_COMMIT(); CP_WAIT0();
        __syncthreads();

        #pragma unroll
        for (int kk = 0; kk < 8; kk++) {
            uint32_t af[2][4];
            #pragma unroll
            for (int i = 0; i < 2; i++) {
                uint32_t ar = (uint32_t)(warpM*32 + i*16 + (lane & 15))*A2_STRIDE
                              + kk*32 + (lane >> 4)*16;
                ldsm4(af[i], sa + ar);
            }
            uint32_t br = (uint32_t)(kk*16 + (lane & 15))*B2_STRIDE
                          + warpN*128 + (lane >> 4)*16;
            uint32_t bf[8][2];
            #pragma unroll
            for (int q = 0; q < 4; q++) {
                uint32_t qq[4];
                ldsm4t(qq, sbb + br + q*32);
                bf[2*q  ][0]=qq[0]; bf[2*q  ][1]=qq[1];
                bf[2*q+1][0]=qq[2]; bf[2*q+1][1]=qq[3];
            }
            #pragma unroll
            for (int i = 0; i < 2; i++)
                #pragma unroll
                for (int g = 0; g < 8; g++)
                    mma16816(acc[i][g], af[i], bf[g]);
        }
        __syncthreads();
    }

    const int qr = lane >> 2;
    const int qc = 2 * (lane & 3);
    #pragma unroll
    for (int i = 0; i < 2; i++)
        #pragma unroll
        for (int g = 0; g < 8; g++) {
            int col = n0 + warpN*64 + g*8 + qc;   // byte offset 128 == 64 columns
            #pragma unroll
            for (int half = 0; half < 2; half++) {
                int tm = warpM*32 + i*16 + qr + half*8;
                if (tm < nrows) {
                    float2 v = make_float2(acc[i][g][half*2], acc[i][g][half*2+1]);
                    *(float2*)(g_dout + (size_t)(row0 + tm)*HID + col) = v;
                }
            }
        }
}

// ---------------- combine ----------------------------------------------------
__global__ void combine_kernel(float* __restrict__ out)
{
    const int t  = blockIdx.x;
    const int s0 = g_token_slot[t*2];
    const int s1 = g_token_slot[t*2+1];
    const float w0 = g_top_w[t*2];
    const float w1 = g_top_w[t*2+1];
    const int h = threadIdx.x << 2;
    float4 d0 = *(const float4*)(g_dout + (size_t)s0*HID + h);
    float4 d1 = *(const float4*)(g_dout + (size_t)s1*HID + h);
    float4 o;
    o.x = w0*d0.x + w1*d1.x;
    o.y = w0*d0.y + w1*d1.y;
    o.z = w0*d0.z + w1*d1.z;
    o.w = w0*d0.w + w1*d1.w;
    *(float4*)(out + (size_t)t*HID + h) = o;
}

// ---------------------------------------------------------------------------
extern "C" void kernel_launch(void* const* d_in, const int* in_sizes, int n_in,
                              void* d_out, int out_size)
{
    const float* x      = (const float*)d_in[0];
    const float* gate_w = (const float*)d_in[1];
    const float* w_gate = (const float*)d_in[2];
    const float* w_up   = (const float*)d_in[3];
    const float* w_down = (const float*)d_in[4];
    float* out = (float*)d_out;

    static int attr_done = 0;
    if (!attr_done) {
        cudaFuncSetAttribute(gemm1_kernel, cudaFuncAttributeMaxDynamicSharedMemorySize, G1_SMEM);
        cudaFuncSetAttribute(gemm2_kernel, cudaFuncAttributeMaxDynamicSharedMemorySize, G2_SMEM);
        attr_done = 1;
    }

    router_kernel<<<NT*32/256, 256>>>(x, gate_w);
    route_build_kernel<<<1, 256>>>();
    {
        dim3 gw((NE*HID*FF/4)/256, 2);     // wg + wu only
        convert_w_kernel<<<gw, 256>>>(w_gate, w_up);
    }
    dim3 g1(MAX_TILES, 1 + FF/BN);     // 40 x 65 (y==0: wd producer blocks)
    gemm1_kernel<<<g1, 256, G1_SMEM>>>(w_down);
    dim3 g2(MAX_TILES, HID/BN2);       // 40 x 8
    gemm2_kernel<<<g2, 256, G2_SMEM>>>();
    combine_kernel<<<NT, 256>>>(out);
}

// round 17
// speedup vs baseline: 2.8019x; 1.0875x over previous
#include <cuda_runtime.h>
#include <cuda_fp16.h>
#include <math.h>
#include <stdint.h>

#define HID   1024
#define FF    4096
#define NE    8
#define NT    2048
#define NSLOT (NT*2)
#define BM    128
#define BN    64
#define MAX_TILES 40

// ---------------- scratch (static device globals; no allocation) ------------
__device__ __align__(256) int   g_top_i[NT*2];
__device__ __align__(256) float g_top_w[NT*2];
__device__ __align__(256) int   g_slot_token[NSLOT];
__device__ __align__(256) int   g_token_slot[NT*2];
__device__ __align__(256) int   g_tile_e[MAX_TILES];
__device__ __align__(256) int   g_tile_row0[MAX_TILES];
__device__ __align__(256) int   g_tile_nrows[MAX_TILES];
__device__ int   g_num_tiles;

// pure fp16 planes
__device__ __align__(256) __half g_x16[NT*HID];
__device__ __align__(256) __half g_wg16[(size_t)NE*HID*FF];
__device__ __align__(256) __half g_wu16[(size_t)NE*HID*FF];
__device__ __align__(256) __half g_wd16[(size_t)NE*FF*HID];
__device__ __align__(256) __half g_h16[(size_t)NSLOT*FF];
__device__ __align__(256) float g_dout[(size_t)NSLOT*HID];

// ---------------- helpers ---------------------------------------------------
__device__ __forceinline__ uint32_t smem_u32(const void* p) {
    uint32_t a;
    asm("{ .reg .u64 t; cvta.to.shared.u64 t, %1; cvt.u32.u64 %0, t; }" : "=r"(a) : "l"(p));
    return a;
}
__device__ __forceinline__ void cp16(uint32_t dst, const void* src) {
    asm volatile("cp.async.cg.shared.global [%0], [%1], 16;"
        :: "r"(dst), "l"(__cvta_generic_to_global(src)) : "memory");
}
#define CP_COMMIT() asm volatile("cp.async.commit_group;" ::: "memory")
#define CP_WAIT1()  asm volatile("cp.async.wait_group 1;" ::: "memory")
#define CP_WAIT0()  asm volatile("cp.async.wait_group 0;" ::: "memory")

__device__ __forceinline__ void ldsm4(uint32_t* r, uint32_t addr) {
    asm volatile("ldmatrix.sync.aligned.m8n8.x4.shared.b16 {%0,%1,%2,%3}, [%4];"
        : "=r"(r[0]), "=r"(r[1]), "=r"(r[2]), "=r"(r[3]) : "r"(addr));
}
__device__ __forceinline__ void ldsm4t(uint32_t* r, uint32_t addr) {
    asm volatile("ldmatrix.sync.aligned.m8n8.x4.trans.shared.b16 {%0,%1,%2,%3}, [%4];"
        : "=r"(r[0]), "=r"(r[1]), "=r"(r[2]), "=r"(r[3]) : "r"(addr));
}
__device__ __forceinline__ void mma16816(float* d, const uint32_t* a, const uint32_t* b) {
    asm volatile("mma.sync.aligned.m16n8k16.row.col.f32.f16.f16.f32 "
        "{%0,%1,%2,%3}, {%4,%5,%6,%7}, {%8,%9}, {%0,%1,%2,%3};"
        : "+f"(d[0]), "+f"(d[1]), "+f"(d[2]), "+f"(d[3])
        : "r"(a[0]), "r"(a[1]), "r"(a[2]), "r"(a[3]), "r"(b[0]), "r"(b[1]));
}
__device__ __forceinline__ uint32_t pack_h2(float a, float b) {
    unsigned short lo = __half_as_ushort(__float2half_rn(a));
    unsigned short hi = __half_as_ushort(__float2half_rn(b));
    return (uint32_t)lo | ((uint32_t)hi << 16);
}

// SMEM strides (bytes): row steps == 4 mod 32 banks -> ldmatrix conflict-free
#define A1_STRIDE 144   // 128B data (64 fp16 = KC) + 16B pad
#define B1_STRIDE 144
#define A2_STRIDE 144
#define B2_STRIDE 272   // 256B data (128 fp16 = BN2) + 16B pad

#define KC 64
#define A1_PLANE (BM*A1_STRIDE)            // 18432
#define B1_PLANE (KC*B1_STRIDE)            // 9216
#define A2_PLANE (BM*A2_STRIDE)            // 18432
#define G1_STAGE (A1_PLANE + 2*B1_PLANE)   // 36864
#define G2_STAGE (A2_PLANE + KC*B2_STRIDE) // 35840
#define G1_SMEM  (2*G1_STAGE)              // 73728
#define G2_SMEM  (2*G2_STAGE)              // 71680

// ---------------- convert: wg + wu only (wd handled inside gemm1 launch) ----
__global__ void convert_w_kernel(const float* __restrict__ wg,
                                 const float* __restrict__ wu)
{
    const float* src = (blockIdx.y == 0) ? wg : wu;
    __half* dst = (blockIdx.y == 0) ? g_wg16 : g_wu16;
    size_t i = (size_t)blockIdx.x * blockDim.x + threadIdx.x;
    float4 v = *(const float4*)(src + i * 4);
    *(uint2*)(dst + i*4) = make_uint2(pack_h2(v.x, v.y), pack_h2(v.z, v.w));
}

// ---------------- router (also emits fp16 x) --------------------------------
__global__ void router_kernel(const float* __restrict__ x, const float* __restrict__ gw)
{
    int wid  = (blockIdx.x * blockDim.x + threadIdx.x) >> 5;
    int lane = threadIdx.x & 31;
    if (wid >= NT) return;
    const float* xr = x + (size_t)wid * HID;
    __half* xo = g_x16 + (size_t)wid * HID;
    float acc[NE];
    #pragma unroll
    for (int e = 0; e < NE; e++) acc[e] = 0.f;
    for (int h = lane; h < HID; h += 32) {
        float  xv = xr[h];
        xo[h] = __float2half_rn(xv);
        float4 a  = *(const float4*)(gw + h*NE);
        float4 b  = *(const float4*)(gw + h*NE + 4);
        acc[0] += xv*a.x; acc[1] += xv*a.y; acc[2] += xv*a.z; acc[3] += xv*a.w;
        acc[4] += xv*b.x; acc[5] += xv*b.y; acc[6] += xv*b.z; acc[7] += xv*b.w;
    }
    #pragma unroll
    for (int e = 0; e < NE; e++)
        #pragma unroll
        for (int o = 16; o > 0; o >>= 1)
            acc[e] += __shfl_xor_sync(0xffffffffu, acc[e], o);
    if (lane == 0) {
        float m = acc[0];
        #pragma unroll
        for (int e = 1; e < NE; e++) m = fmaxf(m, acc[e]);
        float p[NE], s = 0.f;
        #pragma unroll
        for (int e = 0; e < NE; e++) { p[e] = expf(acc[e] - m); s += p[e]; }
        float inv = 1.f / s;
        #pragma unroll
        for (int e = 0; e < NE; e++) p[e] *= inv;
        int i0 = 0;
        #pragma unroll
        for (int e = 1; e < NE; e++) if (p[e] > p[i0]) i0 = e;
        int i1 = (i0 == 0) ? 1 : 0;
        #pragma unroll
        for (int e = 0; e < NE; e++) if (e != i0 && p[e] > p[i1]) i1 = e;
        float w0 = 1.f / (1.f + expf(p[i1] - p[i0]));
        g_top_i[wid*2]   = i0;  g_top_i[wid*2+1] = i1;
        g_top_w[wid*2]   = w0;  g_top_w[wid*2+1] = 1.f - w0;
    }
}

// ---------------- routing build (deterministic) ------------------------------
__global__ void route_build_kernel()
{
    __shared__ int counts[NE];
    __shared__ int offsets[NE+1];
    const int tid  = threadIdx.x;
    const int warp = tid >> 5;
    const int lane = tid & 31;
    int c = 0;
    for (int p = lane; p < NSLOT; p += 32)
        if (g_top_i[p] == warp) c++;
    #pragma unroll
    for (int o = 16; o > 0; o >>= 1) c += __shfl_down_sync(0xffffffffu, c, o);
    if (lane == 0) counts[warp] = c;
    __syncthreads();
    if (tid == 0) {
        int s = 0;
        for (int e = 0; e < NE; e++) { offsets[e] = s; s += counts[e]; }
        offsets[NE] = s;
    }
    __syncthreads();
    int base = offsets[warp];
    for (int p0 = 0; p0 < NSLOT; p0 += 32) {
        int p = p0 + lane;
        bool f = (g_top_i[p] == warp);
        unsigned msk = __ballot_sync(0xffffffffu, f);
        if (f) {
            int slot = base + __popc(msk & ((1u << lane) - 1u));
            g_slot_token[slot] = p >> 1;
            g_token_slot[p]    = slot;
        }
        base += __popc(msk);
    }
    __syncthreads();
    if (tid == 0) {
        int nt = 0;
        for (int e = 0; e < NE; e++) {
            int cnt = counts[e];
            for (int r = 0; r < cnt; r += BM) {
                g_tile_e[nt] = e;
                g_tile_row0[nt] = offsets[e] + r;
                g_tile_nrows[nt] = min(BM, cnt - r);
                nt++;
            }
        }
        g_num_tiles = nt;
    }
}

// ---------------- GEMM1: pipelined fp16, KC=64 x 2 stages, SwiGLU -----------
// grid (MAX_TILES, 1 + FF/BN): y==0 -> wd producer blocks; y>=1 -> gemm tiles.
__global__ void __launch_bounds__(256, 2) gemm1_kernel(const float* __restrict__ wd)
{
    if (blockIdx.y == 0) {
        const size_t total = (size_t)NE*FF*HID/4;
        for (size_t i = (size_t)blockIdx.x*256 + threadIdx.x; i < total;
             i += (size_t)MAX_TILES*256) {
            float4 v = *(const float4*)(wd + i*4);
            *(uint2*)(g_wd16 + i*4) = make_uint2(pack_h2(v.x, v.y), pack_h2(v.z, v.w));
        }
        return;
    }

    const int tile = blockIdx.x;
    if (tile >= g_num_tiles) return;
    const int e     = g_tile_e[tile];
    const int row0  = g_tile_row0[tile];
    const int nrows = g_tile_nrows[tile];
    const int n0    = (blockIdx.y - 1) * BN;

    extern __shared__ __align__(16) char sm[];
    __shared__ int stok[BM];

    const int tid = threadIdx.x, lane = tid & 31, wid = tid >> 5;
    const int warpM = wid & 3, warpN = wid >> 2;

    if (tid < BM) stok[tid] = (tid < nrows) ? g_slot_token[row0 + tid] : 0;
    __syncthreads();

    const __half* bsrc[2] = {
        g_wg16 + (size_t)e*HID*FF, g_wu16 + (size_t)e*HID*FF };

    const uint32_t sb = smem_u32(sm);

    float ag[2][4][4], au[2][4][4];
    #pragma unroll
    for (int i = 0; i < 2; i++)
        #pragma unroll
        for (int g = 0; g < 4; g++)
            #pragma unroll
            for (int r = 0; r < 4; r++) { ag[i][g][r] = 0.f; au[i][g][r] = 0.f; }

    auto load_chunk = [&](int ch, int buf) {
        const uint32_t st = sb + buf * G1_STAGE;
        const int k0 = ch * KC;
        // A: 128 rows x 8 segs = 1024 cp16
        #pragma unroll
        for (int t = 0; t < 4; t++) {
            int idx = tid + t*256;
            int row = idx >> 3, seg = idx & 7;
            cp16(st + row*A1_STRIDE + seg*16,
                 g_x16 + (size_t)stok[row]*HID + k0 + seg*8);
        }
        // B: 2 mats x 64 k-rows x 8 segs = 1024 cp16
        #pragma unroll
        for (int t = 0; t < 4; t++) {
            int idx = tid + t*256;
            int p = idx >> 9, row = (idx >> 3) & 63, seg = idx & 7;
            cp16(st + A1_PLANE + p*B1_PLANE + row*B1_STRIDE + seg*16,
                 bsrc[p] + (size_t)(k0+row)*FF + n0 + seg*8);
        }
        CP_COMMIT();
    };

    const int NCH = HID / KC;     // 16
    load_chunk(0, 0);

    for (int ch = 0; ch < NCH; ch++) {
        if (ch + 1 < NCH) { load_chunk(ch + 1, (ch + 1) & 1); CP_WAIT1(); }
        else              { CP_WAIT0(); }
        __syncthreads();

        const uint32_t st = sb + (ch & 1) * G1_STAGE;
        #pragma unroll
        for (int kk = 0; kk < 4; kk++) {
            uint32_t af[2][4];
            #pragma unroll
            for (int i = 0; i < 2; i++) {
                uint32_t ar = (uint32_t)(warpM*32 + i*16 + (lane & 15))*A1_STRIDE
                              + kk*32 + (lane >> 4)*16;
                ldsm4(af[i], st + ar);
            }
            uint32_t br = (uint32_t)(kk*16 + (lane & 15))*B1_STRIDE
                          + warpN*64 + (lane >> 4)*16;
            uint32_t bf[2][4][2];
            #pragma unroll
            for (int p = 0; p < 2; p++) {
                uint32_t q0[4], q1[4];
                ldsm4t(q0, st + A1_PLANE + p*B1_PLANE + br);
                ldsm4t(q1, st + A1_PLANE + p*B1_PLANE + br + 32);
                bf[p][0][0]=q0[0]; bf[p][0][1]=q0[1];
                bf[p][1][0]=q0[2]; bf[p][1][1]=q0[3];
                bf[p][2][0]=q1[0]; bf[p][2][1]=q1[1];
                bf[p][3][0]=q1[2]; bf[p][3][1]=q1[3];
            }
            #pragma unroll
            for (int i = 0; i < 2; i++)
                #pragma unroll
                for (int g = 0; g < 4; g++) {
                    mma16816(ag[i][g], af[i], bf[0][g]);
                    mma16816(au[i][g], af[i], bf[1][g]);
                }
        }
        __syncthreads();
    }

    const int qr = lane >> 2;
    const int qc = 2 * (lane & 3);
    #pragma unroll
    for (int i = 0; i < 2; i++)
        #pragma unroll
        for (int g = 0; g < 4; g++) {
            int col = n0 + warpN*32 + g*8 + qc;
            #pragma unroll
            for (int half = 0; half < 2; half++) {
                int tm = warpM*32 + i*16 + qr + half*8;
                if (tm < nrows) {
                    float g0 = ag[i][g][half*2],   u0 = au[i][g][half*2];
                    float g1 = ag[i][g][half*2+1], u1 = au[i][g][half*2+1];
                    float v0 = (g0 / (1.f + __expf(-g0))) * u0;
                    float v1 = (g1 / (1.f + __expf(-g1))) * u1;
                    size_t off = (size_t)(row0 + tm) * FF + col;
                    *(uint32_t*)(g_h16 + off) = pack_h2(v0, v1);
                }
            }
        }
}

// ---------------- GEMM2: pipelined fp16 down-proj, BN=128, KC=64 x 2 stages -
#define BN2 128
__global__ void __launch_bounds__(256, 2) gemm2_kernel()
{
    const int tile = blockIdx.x;
    if (tile >= g_num_tiles) return;
    const int e     = g_tile_e[tile];
    const int row0  = g_tile_row0[tile];
    const int nrows = g_tile_nrows[tile];
    const int n0    = blockIdx.y * BN2;

    extern __shared__ __align__(16) char sm[];

    const int tid = threadIdx.x, lane = tid & 31, wid = tid >> 5;
    const int warpM = wid & 3, warpN = wid >> 2;

    const __half* bsrc = g_wd16 + (size_t)e*FF*HID;

    const uint32_t sb = smem_u32(sm);

    float acc[2][8][4];
    #pragma unroll
    for (int i = 0; i < 2; i++)
        #pragma unroll
        for (int g = 0; g < 8; g++)
            #pragma unroll
            for (int r = 0; r < 4; r++) acc[i][g][r] = 0.f;

    auto load_chunk = [&](int ch, int buf) {
        const uint32_t st = sb + buf * G2_STAGE;
        const int k0 = ch * KC;
        // A: 128 rows x 8 segs = 1024 cp16
        #pragma unroll
        for (int t = 0; t < 4; t++) {
            int idx = tid + t*256;
            int row = idx >> 3, seg = idx & 7;
            int r = row0 + row; if (r > NSLOT-1) r = NSLOT-1;
            cp16(st + row*A2_STRIDE + seg*16,
                 g_h16 + (size_t)r*FF + k0 + seg*8);
        }
        // B: 64 k-rows x 16 segs = 1024 cp16
        #pragma unroll
        for (int t = 0; t < 4; t++) {
            int idx = tid + t*256;
            int row = idx >> 4, seg = idx & 15;
            cp16(st + A2_PLANE + row*B2_STRIDE + seg*16,
                 bsrc + (size_t)(k0+row)*HID + n0 + seg*8);
        }
        CP_COMMIT();
    };

    const int NCH = FF / KC;      // 64
    load_chunk(0, 0);

    for (int ch = 0; ch < NCH; ch++) {
        if (ch + 1 < NCH) { load_chunk(ch + 1, (ch + 1) & 1); CP_WAIT1(); }
        else              { CP_WAIT0(); }
        __syncthreads();

        const uint32_t st = sb + (ch & 1) * G2_STAGE;
        #pragma unroll
        for (int kk = 0; kk < 4; kk++) {
            uint32_t af[2][4];
            #pragma unroll
            for (int i = 0; i < 2; i++) {
                uint32_t ar = (uint32_t)(warpM*32 + i*16 + (lane & 15))*A2_STRIDE
                              + kk*32 + (lane >> 4)*16;
                ldsm4(af[i], st + ar);
            }
            uint32_t br = (uint32_t)(kk*16 + (lane & 15))*B2_STRIDE
                          + warpN*128 + (lane >> 4)*16;
            uint32_t bf[8][2];
            #pragma unroll
            for (int q = 0; q < 4; q++) {
                uint32_t qq[4];
                ldsm4t(qq, st + A2_PLANE + br + q*32);
                bf[2*q  ][0]=qq[0]; bf[2*q  ][1]=qq[1];
                bf[2*q+1][0]=qq[2]; bf[2*q+1][1]=qq[3];
            }
            #pragma unroll
            for (int i = 0; i < 2; i++)
                #pragma unroll
                for (int g = 0; g < 8; g++)
                    mma16816(acc[i][g], af[i], bf[g]);
        }
        __syncthreads();
    }

    const int qr = lane >> 2;
    const int qc = 2 * (lane & 3);
    #pragma unroll
    for (int i = 0; i < 2; i++)
        #pragma unroll
        for (int g = 0; g < 8; g++) {
            int col = n0 + warpN*64 + g*8 + qc;
            #pragma unroll
            for (int half = 0; half < 2; half++) {
                int tm = warpM*32 + i*16 + qr + half*8;
                if (tm < nrows) {
                    float2 v = make_float2(acc[i][g][half*2], acc[i][g][half*2+1]);
                    *(float2*)(g_dout + (size_t)(row0 + tm)*HID + col) = v;
                }
            }
        }
}

// ---------------- combine ----------------------------------------------------
__global__ void combine_kernel(float* __restrict__ out)
{
    const int t  = blockIdx.x;
    const int s0 = g_token_slot[t*2];
    const int s1 = g_token_slot[t*2+1];
    const float w0 = g_top_w[t*2];
    const float w1 = g_top_w[t*2+1];
    const int h = threadIdx.x << 2;
    float4 d0 = *(const float4*)(g_dout + (size_t)s0*HID + h);
    float4 d1 = *(const float4*)(g_dout + (size_t)s1*HID + h);
    float4 o;
    o.x = w0*d0.x + w1*d1.x;
    o.y = w0*d0.y + w1*d1.y;
    o.z = w0*d0.z + w1*d1.z;
    o.w = w0*d0.w + w1*d1.w;
    *(float4*)(out + (size_t)t*HID + h) = o;
}

// ---------------------------------------------------------------------------
extern "C" void kernel_launch(void* const* d_in, const int* in_sizes, int n_in,
                              void* d_out, int out_size)
{
    const float* x      = (const float*)d_in[0];
    const float* gate_w = (const float*)d_in[1];
    const float* w_gate = (const float*)d_in[2];
    const float* w_up   = (const float*)d_in[3];
    const float* w_down = (const float*)d_in[4];
    float* out = (float*)d_out;

    static int attr_done = 0;
    if (!attr_done) {
        cudaFuncSetAttribute(gemm1_kernel, cudaFuncAttributeMaxDynamicSharedMemorySize, G1_SMEM);
        cudaFuncSetAttribute(gemm2_kernel, cudaFuncAttributeMaxDynamicSharedMemorySize, G2_SMEM);
        attr_done = 1;
    }

    router_kernel<<<NT*32/256, 256>>>(x, gate_w);
    route_build_kernel<<<1, 256>>>();
    {
        dim3 gw((NE*HID*FF/4)/256, 2);     // wg + wu only
        convert_w_kernel<<<gw, 256>>>(w_gate, w_up);
    }
    dim3 g1(MAX_TILES, 1 + FF/BN);     // 40 x 65 (y==0: wd producer blocks)
    gemm1_kernel<<<g1, 256, G1_SMEM>>>(w_down);
    dim3 g2(MAX_TILES, HID/BN2);       // 40 x 8
    gemm2_kernel<<<g2, 256, G2_SMEM>>>();
    combine_kernel<<<NT, 256>>>(out);
}